// round 5
// baseline (speedup 1.0000x reference)
#include <cuda_runtime.h>
#include <cuda_bf16.h>
#include <cuda_fp8.h>
#include <math.h>
#include <stdint.h>

// Problem constants
#define NB   128
#define TT   32
#define NTOK (128*33)
#define DF   1280
#define WD   256
#define HH   512
#define VV   32000
#define M_NT (NB*TT)      // 4096
#define G4   2048
#define VBM  128
#define VBN  128
#define NTILES_V (VV/VBN) // 250
#define F8SC 16.0f        // fp8 pre-scale for h and W (scores /256 in epilogue)

// ---------------- device scratch ----------------
__device__ __nv_bfloat16 g_hb[(size_t)M_NT * HH];    // h_all bf16, [(n*32+t)][512]
__device__ __nv_fp8_storage_t g_h8[(size_t)M_NT * HH];  // h_all e4m3 (x16)
__device__ __nv_bfloat16 g_wt[(size_t)VV * HH];      // W_vocab bf16 [n][k]
__device__ __nv_fp8_storage_t g_w8[(size_t)VV * HH]; // W_vocab e4m3 [n][k] (x16)
__device__ __nv_bfloat16 g_WxiT[(size_t)G4 * WD];    // gate-interleaved Wx, [n][k] bf16
__device__ __nv_bfloat16 g_WhiT[(size_t)G4 * HH];    // gate-interleaved Wh, [n][k] bf16
__device__ __nv_bfloat16 g_xg[(size_t)M_NT * WD];    // gathered embeddings bf16
__device__ float g_XWx[(size_t)M_NT * G4];           // gate-interleaved x@Wx + b
__device__ float g_h0[NB * HH];
__device__ __nv_bfloat16 g_h0b[NB * HH];
__device__ float g_c[NB * HH];
__device__ float g_bi[G4];
__device__ float g_part[(size_t)M_NT * NTILES_V];
__device__ float g_tsc[M_NT];
__device__ float g_nll[M_NT];
__device__ int   g_rows[M_NT];
__device__ int   g_tgt[M_NT];
__device__ int   g_is64;

// ---------------- small helpers ----------------
__device__ __forceinline__ float sigmoidf_(float x) { return 1.f / (1.f + __expf(-x)); }
__device__ __forceinline__ uint32_t smem_u32(const void* p) {
    return (uint32_t)__cvta_generic_to_shared(p);
}
__device__ __forceinline__ void cp16(void* dst, const void* src) {
    asm volatile("cp.async.cg.shared.global [%0], [%1], 16;"
                 :: "r"(smem_u32(dst)), "l"(src));
}
__device__ __forceinline__ void cp16a(uint32_t dst, const void* src) {
    asm volatile("cp.async.cg.shared.global [%0], [%1], 16;"
                 :: "r"(dst), "l"(src));
}
__device__ __forceinline__ void cp_commit() { asm volatile("cp.async.commit_group;"); }
template<int N> __device__ __forceinline__ void cp_wait() {
    asm volatile("cp.async.wait_group %0;" :: "n"(N));
}
__device__ __forceinline__ void ldsm4(uint32_t& r0, uint32_t& r1, uint32_t& r2, uint32_t& r3, uint32_t addr) {
    asm volatile("ldmatrix.sync.aligned.m8n8.x4.shared.b16 {%0,%1,%2,%3}, [%4];"
                 : "=r"(r0), "=r"(r1), "=r"(r2), "=r"(r3) : "r"(addr));
}
__device__ __forceinline__ void ldsm2(uint32_t& r0, uint32_t& r1, uint32_t addr) {
    asm volatile("ldmatrix.sync.aligned.m8n8.x2.shared.b16 {%0,%1}, [%2];"
                 : "=r"(r0), "=r"(r1) : "r"(addr));
}
__device__ __forceinline__ void mma16816(float* c, const uint32_t* a, const uint32_t* b) {
    asm volatile("mma.sync.aligned.m16n8k16.row.col.f32.bf16.bf16.f32 "
                 "{%0,%1,%2,%3}, {%4,%5,%6,%7}, {%8,%9}, {%0,%1,%2,%3};"
                 : "+f"(c[0]), "+f"(c[1]), "+f"(c[2]), "+f"(c[3])
                 : "r"(a[0]), "r"(a[1]), "r"(a[2]), "r"(a[3]), "r"(b[0]), "r"(b[1]));
}
__device__ __forceinline__ void mma16832f8(float* c, const uint32_t* a, const uint32_t* b) {
    asm volatile("mma.sync.aligned.m16n8k32.row.col.f32.e4m3.e4m3.f32 "
                 "{%0,%1,%2,%3}, {%4,%5,%6,%7}, {%8,%9}, {%0,%1,%2,%3};"
                 : "+f"(c[0]), "+f"(c[1]), "+f"(c[2]), "+f"(c[3])
                 : "r"(a[0]), "r"(a[1]), "r"(a[2]), "r"(a[3]), "r"(b[0]), "r"(b[1]));
}
__device__ __forceinline__ __nv_fp8_storage_t to_e4m3(float x) {
    return __nv_cvt_float_to_fp8(x, __NV_SATFINITE, __NV_E4M3);
}

// ---------------- caption dtype detection + index build ----------------
__global__ void detect_kernel(const unsigned int* __restrict__ w) {
    __shared__ int found;
    if (threadIdx.x == 0) found = 0;
    __syncthreads();
    for (int i = threadIdx.x; i < NTOK / 2; i += blockDim.x)
        if (w[2 * i + 1] != 0u) found = 1;
    __syncthreads();
    if (threadIdx.x == 0) g_is64 = (found == 0) ? 1 : 0;
}

__global__ void build_idx_kernel(const void* __restrict__ caps) {
    int m = blockIdx.x * blockDim.x + threadIdx.x;
    if (m >= M_NT) return;
    int n = m >> 5, t = m & 31;
    int ci, co;
    if (g_is64) {
        const long long* c = (const long long*)caps;
        ci = (int)c[n * 33 + t];  co = (int)c[n * 33 + t + 1];
    } else {
        const int* c = (const int*)caps;
        ci = c[n * 33 + t];       co = c[n * 33 + t + 1];
    }
    g_rows[m] = ci;  g_tgt[m] = co;
}

// ---------------- bias gate-interleave ----------------
__global__ void reorder_bias_kernel(const float* __restrict__ in, float* __restrict__ out) {
    int np = blockIdx.x * blockDim.x + threadIdx.x;
    if (np >= G4) return;
    int j = np >> 2, g = np & 3;
    out[np] = in[g * HH + j];
}

// ---- transpose + gate-interleave + bf16: out[(j*4+g)][k] = in[k][g*512+j] --
__global__ void transT_gate_kernel(const float* __restrict__ in, __nv_bfloat16* __restrict__ out, int K) {
    __shared__ float tile[32][33];
    int np0 = blockIdx.x * 32, k0 = blockIdx.y * 32;
    int tx = threadIdx.x, ty = threadIdx.y;  // 32 x 8
#pragma unroll
    for (int r = 0; r < 4; r++)
        tile[ty + r * 8][tx] = in[(size_t)(k0 + ty + r * 8) * G4 + np0 + tx];
    __syncthreads();
#pragma unroll
    for (int r = 0; r < 4; r++) {
        int npl = ty + r * 8;
        int np = np0 + npl;
        int g = np >> 9, j = np & 511;
        int n = (j << 2) + g;
        out[(size_t)n * K + k0 + tx] = __float2bfloat16(tile[tx][npl]);
    }
}

// ---- W_vocab fp32 [k][n] -> bf16 [n][k] + e4m3 [n][k] (x16) ----------------
__global__ void convW_kernel(const float* __restrict__ Wv) {
    __shared__ float tile[32][33];
    int n0 = blockIdx.x * 32, k0 = blockIdx.y * 32;
    int tx = threadIdx.x, ty = threadIdx.y;
#pragma unroll
    for (int r = 0; r < 4; r++)
        tile[ty + r * 8][tx] = Wv[(size_t)(k0 + ty + r * 8) * VV + n0 + tx];
    __syncthreads();
#pragma unroll
    for (int r = 0; r < 4; r++) {
        int n = ty + r * 8;
        float w = tile[tx][n];
        g_wt[(size_t)(n0 + n) * HH + k0 + tx] = __float2bfloat16(w);
        g_w8[(size_t)(n0 + n) * HH + k0 + tx] = to_e4m3(F8SC * w);
    }
}

// ---- gather + convert embeddings ----
__global__ void gatherconv_kernel(const float* __restrict__ We) {
    int idx = blockIdx.x * blockDim.x + threadIdx.x;
    if (idx >= M_NT * WD) return;
    int m = idx >> 8, k = idx & (WD - 1);
    g_xg[idx] = __float2bfloat16(We[(size_t)g_rows[m] * WD + k]);
}

__global__ void convh0_kernel() {
    int i = blockIdx.x * blockDim.x + threadIdx.x;
    if (i < NB * HH) g_h0b[i] = __float2bfloat16(g_h0[i]);
}

// ---------------- fp32 SGEMM (h0 only) ----------------
template<int BM, int BN, int BK, int TM, int TN>
__global__ void __launch_bounds__(256)
sgemm_k(const float* __restrict__ A, int lda,
        const float* __restrict__ B, int ldb,
        float* __restrict__ C, int ldc,
        const float* __restrict__ bias, int K)
{
    constexpr int THREADS = (BM / TM) * (BN / TN);
    constexpr int ALOAD = BM * BK / THREADS;
    constexpr int BLOAD = BK * BN / THREADS;
    __shared__ float As[BK][BM + 1];
    __shared__ float Bs[BK][BN];
    const int tid = threadIdx.x;
    const int tx = tid % (BN / TN);
    const int ty = tid / (BN / TN);
    const int m0 = blockIdx.y * BM;
    const int n0 = blockIdx.x * BN;

    float acc[TM][TN];
#pragma unroll
    for (int i = 0; i < TM; i++)
#pragma unroll
        for (int j = 0; j < TN; j++) acc[i][j] = 0.f;

    for (int k0 = 0; k0 < K; k0 += BK) {
#pragma unroll
        for (int l = 0; l < ALOAD; l++) {
            int idx = tid + l * THREADS;
            int k = idx % BK, m = idx / BK;
            As[k][m] = A[(size_t)(m0 + m) * lda + k0 + k];
        }
#pragma unroll
        for (int l = 0; l < BLOAD; l++) {
            int idx = tid + l * THREADS;
            int n = idx % BN, k = idx / BN;
            Bs[k][n] = B[(size_t)(k0 + k) * ldb + n0 + n];
        }
        __syncthreads();
#pragma unroll
        for (int kk = 0; kk < BK; kk++) {
            float a[TM], b[TN];
#pragma unroll
            for (int i = 0; i < TM; i++) a[i] = As[kk][ty * TM + i];
#pragma unroll
            for (int j = 0; j < TN; j++) b[j] = Bs[kk][tx * TN + j];
#pragma unroll
            for (int i = 0; i < TM; i++)
#pragma unroll
                for (int j = 0; j < TN; j++) acc[i][j] += a[i] * b[j];
        }
        __syncthreads();
    }
#pragma unroll
    for (int i = 0; i < TM; i++)
#pragma unroll
        for (int j = 0; j < TN; j++) {
            int n = n0 + tx * TN + j;
            C[(size_t)(m0 + ty * TM + i) * ldc + n] = acc[i][j] + bias[n];
        }
}

// ---------------- XWx bf16 MMA ----------------
__global__ void __launch_bounds__(256)
xwx_mma_kernel() {
    __shared__ __align__(16) __nv_bfloat16 As[2][128][40];
    __shared__ __align__(16) __nv_bfloat16 Bs[2][128][40];
    int tid = threadIdx.x;
    int lane = tid & 31, wid = tid >> 5;
    int wm = wid & 1, wn = wid >> 1;
    int m0 = blockIdx.x * 128;
    int n0 = blockIdx.y * 128;

    float acc[4][4][4];
#pragma unroll
    for (int a = 0; a < 4; a++)
#pragma unroll
        for (int b = 0; b < 4; b++)
#pragma unroll
            for (int c = 0; c < 4; c++) acc[a][b][c] = 0.f;

    auto loadA = [&](int s, int k0) {
#pragma unroll
        for (int l = 0; l < 2; l++) {
            int idx = tid + l * 256;
            int row = idx >> 2, ch = idx & 3;
            cp16(&As[s][row][ch * 8], g_xg + (size_t)(m0 + row) * WD + k0 + ch * 8);
        }
    };
    auto loadB = [&](int s, int k0) {
#pragma unroll
        for (int l = 0; l < 2; l++) {
            int idx = tid + l * 256;
            int row = idx >> 2, ch = idx & 3;
            cp16(&Bs[s][row][ch * 8], g_WxiT + (size_t)(n0 + row) * WD + k0 + ch * 8);
        }
    };
    loadA(0, 0); loadB(0, 0); cp_commit();

    constexpr int NIT = WD / 32;  // 8
    for (int it = 0; it < NIT; it++) {
        if (it + 1 < NIT) {
            int s = (it + 1) & 1;
            loadA(s, (it + 1) * 32); loadB(s, (it + 1) * 32);
            cp_commit(); cp_wait<1>();
        } else cp_wait<0>();
        __syncthreads();
        int s = it & 1;
        uint32_t aBase = smem_u32(&As[s][0][0]);
        uint32_t bBase = smem_u32(&Bs[s][0][0]);
#pragma unroll
        for (int ks = 0; ks < 2; ks++) {
            uint32_t a[4][4], b[4][2];
#pragma unroll
            for (int mf = 0; mf < 4; mf++) {
                int row = wm * 64 + mf * 16 + (lane & 15);
                ldsm4(a[mf][0], a[mf][1], a[mf][2], a[mf][3],
                      aBase + row * 80 + (ks * 16 + (lane >> 4) * 8) * 2);
            }
#pragma unroll
            for (int nf = 0; nf < 4; nf++) {
                int row = wn * 32 + nf * 8 + (lane & 7);
                ldsm2(b[nf][0], b[nf][1],
                      bBase + row * 80 + (ks * 16 + ((lane >> 3) & 1) * 8) * 2);
            }
#pragma unroll
            for (int mf = 0; mf < 4; mf++)
#pragma unroll
                for (int nf = 0; nf < 4; nf++)
                    mma16816(acc[mf][nf], a[mf], b[nf]);
        }
        __syncthreads();
    }

#pragma unroll
    for (int mf = 0; mf < 4; mf++) {
        int r = m0 + wm * 64 + mf * 16 + (lane >> 2);
#pragma unroll
        for (int nf = 0; nf < 4; nf++) {
            int c = n0 + wn * 32 + nf * 8 + 2 * (lane & 3);
            float b0 = g_bi[c], b1 = g_bi[c + 1];
            float2 v0 = {acc[mf][nf][0] + b0, acc[mf][nf][1] + b1};
            float2 v1 = {acc[mf][nf][2] + b0, acc[mf][nf][3] + b1};
            *(float2*)&g_XWx[(size_t)r * G4 + c] = v0;
            *(float2*)&g_XWx[(size_t)(r + 8) * G4 + c] = v1;
        }
    }
}

// ---------------- LSTM step: bf16 MMA + fused gates ----------------
__global__ void __launch_bounds__(256)
lstm_mma_step(const __nv_bfloat16* __restrict__ Aptr, int rowStride, int t) {
    __shared__ __align__(16) __nv_bfloat16 As[2][128][40];
    __shared__ __align__(16) __nv_bfloat16 Bs[2][32][40];
    int tid = threadIdx.x;
    int lane = tid & 31, wid = tid >> 5;
    int wm = wid >> 2, wn = wid & 3;
    int n0 = blockIdx.x * 32;

    float acc[4][4];
#pragma unroll
    for (int a = 0; a < 4; a++)
#pragma unroll
        for (int c = 0; c < 4; c++) acc[a][c] = 0.f;

    auto loadA = [&](int s, int k0) {
#pragma unroll
        for (int l = 0; l < 2; l++) {
            int idx = tid + l * 256;
            int row = idx >> 2, ch = idx & 3;
            cp16(&As[s][row][ch * 8], Aptr + (size_t)row * rowStride + k0 + ch * 8);
        }
    };
    auto loadB = [&](int s, int k0) {
        if (tid < 128) {
            int row = tid >> 2, ch = tid & 3;
            cp16(&Bs[s][row][ch * 8], g_WhiT + (size_t)(n0 + row) * HH + k0 + ch * 8);
        }
    };
    loadA(0, 0); loadB(0, 0); cp_commit();

    constexpr int NIT = HH / 32;  // 16
    for (int it = 0; it < NIT; it++) {
        if (it + 1 < NIT) {
            int s = (it + 1) & 1;
            loadA(s, (it + 1) * 32); loadB(s, (it + 1) * 32);
            cp_commit(); cp_wait<1>();
        } else cp_wait<0>();
        __syncthreads();
        int s = it & 1;
        uint32_t aBase = smem_u32(&As[s][0][0]);
        uint32_t bBase = smem_u32(&Bs[s][0][0]);
#pragma unroll
        for (int ks = 0; ks < 2; ks++) {
            uint32_t a[4][4], b[2];
#pragma unroll
            for (int mf = 0; mf < 4; mf++) {
                int row = wm * 64 + mf * 16 + (lane & 15);
                ldsm4(a[mf][0], a[mf][1], a[mf][2], a[mf][3],
                      aBase + row * 80 + (ks * 16 + (lane >> 4) * 8) * 2);
            }
            {
                int row = wn * 8 + (lane & 7);
                ldsm2(b[0], b[1],
                      bBase + row * 80 + (ks * 16 + ((lane >> 3) & 1) * 8) * 2);
            }
#pragma unroll
            for (int mf = 0; mf < 4; mf++)
                mma16816(acc[mf], a[mf], b);
        }
        __syncthreads();
    }

    int cbase = n0 + wn * 8 + 2 * (lane & 3);
    int j = cbase >> 2;
#pragma unroll
    for (int mf = 0; mf < 4; mf++) {
        int r = wm * 64 + mf * 16 + (lane >> 2);
        float2 x0 = *(const float2*)&g_XWx[(size_t)((r << 5) + t) * G4 + cbase];
        float2 x1 = *(const float2*)&g_XWx[(size_t)(((r + 8) << 5) + t) * G4 + cbase];
        float v0 = acc[mf][0] + x0.x, v1 = acc[mf][1] + x0.y;
        float v2 = acc[mf][2] + x1.x, v3 = acc[mf][3] + x1.y;
        float e0 = __shfl_xor_sync(0xffffffffu, v0, 1);
        float e1 = __shfl_xor_sync(0xffffffffu, v1, 1);
        float e2 = __shfl_xor_sync(0xffffffffu, v2, 1);
        float e3 = __shfl_xor_sync(0xffffffffu, v3, 1);
        if (!(lane & 1)) {
            {
                float i_ = sigmoidf_(v0), f_ = sigmoidf_(v1);
                float o_ = sigmoidf_(e0), gg = tanhf(e1);
                float cp = t ? g_c[r * HH + j] : 0.f;
                float cn = f_ * cp + i_ * gg;
                float hv = o_ * tanhf(cn);
                g_c[r * HH + j] = cn;
                size_t hi = (size_t)((r << 5) + t) * HH + j;
                g_hb[hi] = __float2bfloat16(hv);
                g_h8[hi] = to_e4m3(F8SC * hv);
            }
            {
                int r8 = r + 8;
                float i_ = sigmoidf_(v2), f_ = sigmoidf_(v3);
                float o_ = sigmoidf_(e2), gg = tanhf(e3);
                float cp = t ? g_c[r8 * HH + j] : 0.f;
                float cn = f_ * cp + i_ * gg;
                float hv = o_ * tanhf(cn);
                g_c[r8 * HH + j] = cn;
                size_t hi = (size_t)((r8 << 5) + t) * HH + j;
                g_hb[hi] = __float2bfloat16(hv);
                g_h8[hi] = to_e4m3(F8SC * hv);
            }
        }
    }
}

// ---------------- vocab FP8 MMA GEMM + fused sum-exp epilogue ---------------
// Block 128x128, K=512 in 8 chunks of 64 fp8 (64B rows, 80B padded).
// Fragment layouts identical to the bf16 k16 kernel (b16 elem = 2 packed fp8).
__global__ void __launch_bounds__(256)
vocab_f8_kernel(const float* __restrict__ bv) {
    __shared__ __align__(16) uint8_t As[2][VBM][80];
    __shared__ __align__(16) uint8_t Bs[2][VBN][80];
    __shared__ float sred[4][VBM];
    int tid = threadIdx.x;
    int lane = tid & 31, wid = tid >> 5;
    int wm = wid & 1, wn = wid >> 1;          // warp tile 64m x 32n
    int m0 = blockIdx.x * VBM;
    int n0 = blockIdx.y * VBN;

    float acc[4][4][4];
#pragma unroll
    for (int a = 0; a < 4; a++)
#pragma unroll
        for (int b = 0; b < 4; b++)
#pragma unroll
            for (int c = 0; c < 4; c++) acc[a][b][c] = 0.f;

    auto loadA = [&](int s, int k0) {
#pragma unroll
        for (int l = 0; l < 2; l++) {
            int idx = tid + l * 256;
            int row = idx >> 2, ch = idx & 3;
            cp16(&As[s][row][ch * 16], g_h8 + (size_t)(m0 + row) * HH + k0 + ch * 16);
        }
    };
    auto loadB = [&](int s, int k0) {
#pragma unroll
        for (int l = 0; l < 2; l++) {
            int idx = tid + l * 256;
            int row = idx >> 2, ch = idx & 3;
            cp16(&Bs[s][row][ch * 16], g_w8 + (size_t)(n0 + row) * HH + k0 + ch * 16);
        }
    };
    loadA(0, 0); loadB(0, 0); cp_commit();

    constexpr int NIT = HH / 64;  // 8 chunks of 64 fp8
    for (int it = 0; it < NIT; it++) {
        if (it + 1 < NIT) {
            int s = (it + 1) & 1;
            loadA(s, (it + 1) * 64); loadB(s, (it + 1) * 64);
            cp_commit(); cp_wait<1>();
        } else cp_wait<0>();
        __syncthreads();
        int s = it & 1;
        uint32_t aBase = smem_u32(&As[s][0][0]);
        uint32_t bBase = smem_u32(&Bs[s][0][0]);
#pragma unroll
        for (int ks = 0; ks < 2; ks++) {         // two k32 mma steps per chunk
            uint32_t a[4][4], b[4][2];
#pragma unroll
            for (int mf = 0; mf < 4; mf++) {
                int row = wm * 64 + mf * 16 + (lane & 15);
                ldsm4(a[mf][0], a[mf][1], a[mf][2], a[mf][3],
                      aBase + row * 80 + ks * 32 + (lane >> 4) * 16);
            }
#pragma unroll
            for (int nf = 0; nf < 4; nf++) {
                int row = wn * 32 + nf * 8 + (lane & 7);
                ldsm2(b[nf][0], b[nf][1],
                      bBase + row * 80 + ks * 32 + ((lane >> 3) & 1) * 16);
            }
#pragma unroll
            for (int mf = 0; mf < 4; mf++)
#pragma unroll
                for (int nf = 0; nf < 4; nf++)
                    mma16832f8(acc[mf][nf], a[mf], b[nf]);
        }
        __syncthreads();
    }

    // epilogue: scores = acc/256 + bias; sum exp per row
    const float INV = 1.f / (F8SC * F8SC);
    float rowsum[4][2] = {};
#pragma unroll
    for (int nf = 0; nf < 4; nf++) {
        int nb_ = n0 + wn * 32 + nf * 8 + 2 * (lane & 3);
        float b0 = bv[nb_], b1 = bv[nb_ + 1];
#pragma unroll
        for (int mf = 0; mf < 4; mf++) {
            rowsum[mf][0] += __expf(fmaf(acc[mf][nf][0], INV, b0))
                           + __expf(fmaf(acc[mf][nf][1], INV, b1));
            rowsum[mf][1] += __expf(fmaf(acc[mf][nf][2], INV, b0))
                           + __expf(fmaf(acc[mf][nf][3], INV, b1));
        }
    }
#pragma unroll
    for (int mf = 0; mf < 4; mf++)
#pragma unroll
        for (int h = 0; h < 2; h++) {
            rowsum[mf][h] += __shfl_xor_sync(0xffffffffu, rowsum[mf][h], 1);
            rowsum[mf][h] += __shfl_xor_sync(0xffffffffu, rowsum[mf][h], 2);
        }
    if ((lane & 3) == 0) {
#pragma unroll
        for (int mf = 0; mf < 4; mf++) {
            int r = wm * 64 + mf * 16 + (lane >> 2);
            sred[wn][r]     = rowsum[mf][0];
            sred[wn][r + 8] = rowsum[mf][1];
        }
    }
    __syncthreads();
    if (tid < VBM) {
        float s = sred[0][tid] + sred[1][tid] + sred[2][tid] + sred[3][tid];
        g_part[(size_t)(m0 + tid) * NTILES_V + blockIdx.y] = s;
    }
}

// ---------------- target scores (coalesced bf16) ----------------
__global__ void tscore_kernel(const float* __restrict__ bv) {
    int w = (blockIdx.x * blockDim.x + threadIdx.x) >> 5;
    int lane = threadIdx.x & 31;
    if (w >= M_NT) return;
    int tgt = g_tgt[w];
    const uint4* h4 = (const uint4*)(g_hb + (size_t)w * HH);
    const uint4* w4 = (const uint4*)(g_wt + (size_t)tgt * HH);
    float s = 0.f;
#pragma unroll
    for (int i = 0; i < 2; i++) {
        uint4 a = h4[lane + i * 32];
        uint4 b = w4[lane + i * 32];
        const uint32_t* ap = &a.x;
        const uint32_t* bp = &b.x;
#pragma unroll
        for (int q = 0; q < 4; q++) {
            float2 fa = __bfloat1622float2(*(const __nv_bfloat162*)&ap[q]);
            float2 fb = __bfloat1622float2(*(const __nv_bfloat162*)&bp[q]);
            s += fa.x * fb.x + fa.y * fb.y;
        }
    }
#pragma unroll
    for (int off = 16; off; off >>= 1) s += __shfl_down_sync(0xffffffffu, s, off);
    if (lane == 0) g_tsc[w] = s + bv[tgt];
}

// ---------------- per-token nll + final loss ----------------
__global__ void nll_kernel() {
    int w = (blockIdx.x * blockDim.x + threadIdx.x) >> 5;
    int lane = threadIdx.x & 31;
    if (w >= M_NT) return;
    const float* p = g_part + (size_t)w * NTILES_V;
    float s = 0.f;
    for (int i = lane; i < NTILES_V; i += 32) s += p[i];
#pragma unroll
    for (int off = 16; off; off >>= 1) s += __shfl_down_sync(0xffffffffu, s, off);
    if (lane == 0)
        g_nll[w] = (g_tgt[w] != 0) ? (logf(s) - g_tsc[w]) : 0.f;
}

__global__ void loss_kernel(float* __restrict__ out) {
    __shared__ float sm[256];
    float s = 0.f;
    for (int i = threadIdx.x; i < M_NT; i += 256) s += g_nll[i];
    sm[threadIdx.x] = s;
    __syncthreads();
    for (int off = 128; off; off >>= 1) {
        if (threadIdx.x < off) sm[threadIdx.x] += sm[threadIdx.x + off];
        __syncthreads();
    }
    if (threadIdx.x == 0) out[0] = sm[0] / (float)NB;
}

// ---------------- launch ----------------
extern "C" void kernel_launch(void* const* d_in, const int* in_sizes, int n_in,
                              void* d_out, int out_size) {
    const float* features = (const float*)d_in[0];
    const void*  captions =               d_in[1];
    const float* W_proj   = (const float*)d_in[2];
    const float* b_proj   = (const float*)d_in[3];
    const float* W_embed  = (const float*)d_in[4];
    const float* Wx       = (const float*)d_in[5];
    const float* Wh       = (const float*)d_in[6];
    const float* bb       = (const float*)d_in[7];
    const float* W_vocab  = (const float*)d_in[8];
    const float* b_vocab  = (const float*)d_in[9];
    float* out = (float*)d_out;

    float *p_h0, *p_bi;
    __nv_bfloat16 *p_WxiT, *p_WhiT, *p_h0b, *p_hb;
    cudaGetSymbolAddress((void**)&p_h0,   g_h0);
    cudaGetSymbolAddress((void**)&p_bi,   g_bi);
    cudaGetSymbolAddress((void**)&p_WxiT, g_WxiT);
    cudaGetSymbolAddress((void**)&p_WhiT, g_WhiT);
    cudaGetSymbolAddress((void**)&p_h0b,  g_h0b);
    cudaGetSymbolAddress((void**)&p_hb,   g_hb);

    // 0. indices + weight conversions
    detect_kernel<<<1, 256>>>((const unsigned int*)captions);
    build_idx_kernel<<<(M_NT + 255) / 256, 256>>>(captions);
    reorder_bias_kernel<<<(G4 + 255) / 256, 256>>>(bb, p_bi);
    transT_gate_kernel<<<dim3(G4 / 32, WD / 32), dim3(32, 8)>>>(Wx, p_WxiT, WD);
    transT_gate_kernel<<<dim3(G4 / 32, HH / 32), dim3(32, 8)>>>(Wh, p_WhiT, HH);
    convW_kernel<<<dim3(VV / 32, HH / 32), dim3(32, 8)>>>(W_vocab);
    gatherconv_kernel<<<(M_NT * WD + 255) / 256, 256>>>(W_embed);

    // 1. h0
    sgemm_k<32, 64, 16, 2, 4><<<dim3(HH / 64, NB / 32), 256>>>(
        features, DF, W_proj, HH, p_h0, HH, b_proj, DF);
    convh0_kernel<<<(NB * HH + 255) / 256, 256>>>();

    // 2. XWx
    xwx_mma_kernel<<<dim3(M_NT / 128, G4 / 128), 256>>>();

    // 3. LSTM
    for (int t = 0; t < TT; t++) {
        const __nv_bfloat16* Aptr = (t == 0) ? p_h0b : (p_hb + (size_t)(t - 1) * HH);
        int stride = (t == 0) ? HH : (TT * HH);
        lstm_mma_step<<<G4 / 32, 256>>>(Aptr, stride, t);
    }

    // 4. vocab FP8 MMA GEMM + fused sum-exp
    vocab_f8_kernel<<<dim3(M_NT / VBM, NTILES_V), 256>>>(b_vocab);

    // 5. target scores, per-token nll, final loss
    tscore_kernel<<<M_NT / 4, 128>>>(b_vocab);
    nll_kernel<<<M_NT / 4, 128>>>();
    loss_kernel<<<1, 256>>>(out);
}

// round 7
// speedup vs baseline: 1.0309x; 1.0309x over previous
#include <cuda_runtime.h>
#include <cuda_bf16.h>
#include <math.h>
#include <stdint.h>

// Problem constants
#define NB   128
#define TT   32
#define NTOK (128*33)
#define DF   1280
#define WD   256
#define HH   512
#define VV   32000
#define M_NT (NB*TT)      // 4096
#define G4   2048
#define VBM  128
#define VBN  256
#define NTILES_V (VV/VBN) // 125

// Vocab kernel dynamic smem layout (bytes):
//   As: 2*128*40*2 = 20480 | Bs: 2*256*40*2 = 40960 | sred: 4*128*4 = 2048
#define VAS_B   (2 * VBM * 40 * 2)
#define VBS_B   (2 * VBN * 40 * 2)
#define VSMEM   (VAS_B + VBS_B + 4 * VBM * 4)

// ---------------- device scratch ----------------
__device__ __nv_bfloat16 g_hb[(size_t)M_NT * HH];    // h_all bf16, [(n*32+t)][512]
__device__ __nv_bfloat16 g_wt[(size_t)VV * HH];      // W_vocab bf16 [n][k]
__device__ __nv_bfloat16 g_WxiT[(size_t)G4 * WD];    // gate-interleaved Wx, [n][k] bf16
__device__ __nv_bfloat16 g_WhiT[(size_t)G4 * HH];    // gate-interleaved Wh, [n][k] bf16
__device__ __nv_bfloat16 g_xg[(size_t)M_NT * WD];    // gathered embeddings bf16
__device__ float g_XWx[(size_t)M_NT * G4];           // gate-interleaved x@Wx + b
__device__ float g_h0[NB * HH];
__device__ __nv_bfloat16 g_h0b[NB * HH];
__device__ float g_c[NB * HH];
__device__ float g_bi[G4];
__device__ float g_part[(size_t)M_NT * NTILES_V];
__device__ float g_tsc[M_NT];
__device__ float g_nll[M_NT];
__device__ int   g_rows[M_NT];
__device__ int   g_tgt[M_NT];
__device__ int   g_is64;

// ---------------- small helpers ----------------
__device__ __forceinline__ float sigmoidf_(float x) { return 1.f / (1.f + __expf(-x)); }
__device__ __forceinline__ uint32_t smem_u32(const void* p) {
    return (uint32_t)__cvta_generic_to_shared(p);
}
__device__ __forceinline__ void cp16(void* dst, const void* src) {
    asm volatile("cp.async.cg.shared.global [%0], [%1], 16;"
                 :: "r"(smem_u32(dst)), "l"(src));
}
__device__ __forceinline__ void cp_commit() { asm volatile("cp.async.commit_group;"); }
template<int N> __device__ __forceinline__ void cp_wait() {
    asm volatile("cp.async.wait_group %0;" :: "n"(N));
}
__device__ __forceinline__ void ldsm4(uint32_t& r0, uint32_t& r1, uint32_t& r2, uint32_t& r3, uint32_t addr) {
    asm volatile("ldmatrix.sync.aligned.m8n8.x4.shared.b16 {%0,%1,%2,%3}, [%4];"
                 : "=r"(r0), "=r"(r1), "=r"(r2), "=r"(r3) : "r"(addr));
}
__device__ __forceinline__ void ldsm2(uint32_t& r0, uint32_t& r1, uint32_t addr) {
    asm volatile("ldmatrix.sync.aligned.m8n8.x2.shared.b16 {%0,%1}, [%2];"
                 : "=r"(r0), "=r"(r1) : "r"(addr));
}
__device__ __forceinline__ void mma16816(float* c, const uint32_t* a, const uint32_t* b) {
    asm volatile("mma.sync.aligned.m16n8k16.row.col.f32.bf16.bf16.f32 "
                 "{%0,%1,%2,%3}, {%4,%5,%6,%7}, {%8,%9}, {%0,%1,%2,%3};"
                 : "+f"(c[0]), "+f"(c[1]), "+f"(c[2]), "+f"(c[3])
                 : "r"(a[0]), "r"(a[1]), "r"(a[2]), "r"(a[3]), "r"(b[0]), "r"(b[1]));
}

// ---------------- caption dtype detection + index build ----------------
__global__ void detect_kernel(const unsigned int* __restrict__ w) {
    __shared__ int found;
    if (threadIdx.x == 0) found = 0;
    __syncthreads();
    for (int i = threadIdx.x; i < NTOK / 2; i += blockDim.x)
        if (w[2 * i + 1] != 0u) found = 1;
    __syncthreads();
    if (threadIdx.x == 0) g_is64 = (found == 0) ? 1 : 0;
}

__global__ void build_idx_kernel(const void* __restrict__ caps) {
    int m = blockIdx.x * blockDim.x + threadIdx.x;
    if (m >= M_NT) return;
    int n = m >> 5, t = m & 31;
    int ci, co;
    if (g_is64) {
        const long long* c = (const long long*)caps;
        ci = (int)c[n * 33 + t];  co = (int)c[n * 33 + t + 1];
    } else {
        const int* c = (const int*)caps;
        ci = c[n * 33 + t];       co = c[n * 33 + t + 1];
    }
    g_rows[m] = ci;  g_tgt[m] = co;
}

// ---------------- bias gate-interleave ----------------
__global__ void reorder_bias_kernel(const float* __restrict__ in, float* __restrict__ out) {
    int np = blockIdx.x * blockDim.x + threadIdx.x;
    if (np >= G4) return;
    int j = np >> 2, g = np & 3;
    out[np] = in[g * HH + j];
}

// ---- transpose + gate-interleave + bf16: out[(j*4+g)][k] = in[k][g*512+j] --
__global__ void transT_gate_kernel(const float* __restrict__ in, __nv_bfloat16* __restrict__ out, int K) {
    __shared__ float tile[32][33];
    int np0 = blockIdx.x * 32, k0 = blockIdx.y * 32;
    int tx = threadIdx.x, ty = threadIdx.y;  // 32 x 8
#pragma unroll
    for (int r = 0; r < 4; r++)
        tile[ty + r * 8][tx] = in[(size_t)(k0 + ty + r * 8) * G4 + np0 + tx];
    __syncthreads();
#pragma unroll
    for (int r = 0; r < 4; r++) {
        int npl = ty + r * 8;
        int np = np0 + npl;
        int g = np >> 9, j = np & 511;
        int n = (j << 2) + g;
        out[(size_t)n * K + k0 + tx] = __float2bfloat16(tile[tx][npl]);
    }
}

// ---- W_vocab fp32 [k][n] -> bf16 [n][k] -----------------------------------
__global__ void convW_kernel(const float* __restrict__ Wv) {
    __shared__ float tile[32][33];
    int n0 = blockIdx.x * 32, k0 = blockIdx.y * 32;
    int tx = threadIdx.x, ty = threadIdx.y;
#pragma unroll
    for (int r = 0; r < 4; r++)
        tile[ty + r * 8][tx] = Wv[(size_t)(k0 + ty + r * 8) * VV + n0 + tx];
    __syncthreads();
#pragma unroll
    for (int r = 0; r < 4; r++) {
        int n = ty + r * 8;
        g_wt[(size_t)(n0 + n) * HH + k0 + tx] = __float2bfloat16(tile[tx][n]);
    }
}

// ---- gather + convert embeddings ----
__global__ void gatherconv_kernel(const float* __restrict__ We) {
    int idx = blockIdx.x * blockDim.x + threadIdx.x;
    if (idx >= M_NT * WD) return;
    int m = idx >> 8, k = idx & (WD - 1);
    g_xg[idx] = __float2bfloat16(We[(size_t)g_rows[m] * WD + k]);
}

__global__ void convh0_kernel() {
    int i = blockIdx.x * blockDim.x + threadIdx.x;
    if (i < NB * HH) g_h0b[i] = __float2bfloat16(g_h0[i]);
}

// ---------------- fp32 SGEMM (h0 only) ----------------
template<int BM, int BN, int BK, int TM, int TN>
__global__ void __launch_bounds__(256)
sgemm_k(const float* __restrict__ A, int lda,
        const float* __restrict__ B, int ldb,
        float* __restrict__ C, int ldc,
        const float* __restrict__ bias, int K)
{
    constexpr int THREADS = (BM / TM) * (BN / TN);
    constexpr int ALOAD = BM * BK / THREADS;
    constexpr int BLOAD = BK * BN / THREADS;
    __shared__ float As[BK][BM + 1];
    __shared__ float Bs[BK][BN];
    const int tid = threadIdx.x;
    const int tx = tid % (BN / TN);
    const int ty = tid / (BN / TN);
    const int m0 = blockIdx.y * BM;
    const int n0 = blockIdx.x * BN;

    float acc[TM][TN];
#pragma unroll
    for (int i = 0; i < TM; i++)
#pragma unroll
        for (int j = 0; j < TN; j++) acc[i][j] = 0.f;

    for (int k0 = 0; k0 < K; k0 += BK) {
#pragma unroll
        for (int l = 0; l < ALOAD; l++) {
            int idx = tid + l * THREADS;
            int k = idx % BK, m = idx / BK;
            As[k][m] = A[(size_t)(m0 + m) * lda + k0 + k];
        }
#pragma unroll
        for (int l = 0; l < BLOAD; l++) {
            int idx = tid + l * THREADS;
            int n = idx % BN, k = idx / BN;
            Bs[k][n] = B[(size_t)(k0 + k) * ldb + n0 + n];
        }
        __syncthreads();
#pragma unroll
        for (int kk = 0; kk < BK; kk++) {
            float a[TM], b[TN];
#pragma unroll
            for (int i = 0; i < TM; i++) a[i] = As[kk][ty * TM + i];
#pragma unroll
            for (int j = 0; j < TN; j++) b[j] = Bs[kk][tx * TN + j];
#pragma unroll
            for (int i = 0; i < TM; i++)
#pragma unroll
                for (int j = 0; j < TN; j++) acc[i][j] += a[i] * b[j];
        }
        __syncthreads();
    }
#pragma unroll
    for (int i = 0; i < TM; i++)
#pragma unroll
        for (int j = 0; j < TN; j++) {
            int n = n0 + tx * TN + j;
            C[(size_t)(m0 + ty * TM + i) * ldc + n] = acc[i][j] + bias[n];
        }
}

// ---------------- XWx bf16 MMA ----------------
__global__ void __launch_bounds__(256)
xwx_mma_kernel() {
    __shared__ __align__(16) __nv_bfloat16 As[2][128][40];
    __shared__ __align__(16) __nv_bfloat16 Bs[2][128][40];
    int tid = threadIdx.x;
    int lane = tid & 31, wid = tid >> 5;
    int wm = wid & 1, wn = wid >> 1;
    int m0 = blockIdx.x * 128;
    int n0 = blockIdx.y * 128;

    float acc[4][4][4];
#pragma unroll
    for (int a = 0; a < 4; a++)
#pragma unroll
        for (int b = 0; b < 4; b++)
#pragma unroll
            for (int c = 0; c < 4; c++) acc[a][b][c] = 0.f;

    auto loadA = [&](int s, int k0) {
#pragma unroll
        for (int l = 0; l < 2; l++) {
            int idx = tid + l * 256;
            int row = idx >> 2, ch = idx & 3;
            cp16(&As[s][row][ch * 8], g_xg + (size_t)(m0 + row) * WD + k0 + ch * 8);
        }
    };
    auto loadB = [&](int s, int k0) {
#pragma unroll
        for (int l = 0; l < 2; l++) {
            int idx = tid + l * 256;
            int row = idx >> 2, ch = idx & 3;
            cp16(&Bs[s][row][ch * 8], g_WxiT + (size_t)(n0 + row) * WD + k0 + ch * 8);
        }
    };
    loadA(0, 0); loadB(0, 0); cp_commit();

    constexpr int NIT = WD / 32;  // 8
    for (int it = 0; it < NIT; it++) {
        if (it + 1 < NIT) {
            int s = (it + 1) & 1;
            loadA(s, (it + 1) * 32); loadB(s, (it + 1) * 32);
            cp_commit(); cp_wait<1>();
        } else cp_wait<0>();
        __syncthreads();
        int s = it & 1;
        uint32_t aBase = smem_u32(&As[s][0][0]);
        uint32_t bBase = smem_u32(&Bs[s][0][0]);
#pragma unroll
        for (int ks = 0; ks < 2; ks++) {
            uint32_t a[4][4], b[4][2];
#pragma unroll
            for (int mf = 0; mf < 4; mf++) {
                int row = wm * 64 + mf * 16 + (lane & 15);
                ldsm4(a[mf][0], a[mf][1], a[mf][2], a[mf][3],
                      aBase + row * 80 + (ks * 16 + (lane >> 4) * 8) * 2);
            }
#pragma unroll
            for (int nf = 0; nf < 4; nf++) {
                int row = wn * 32 + nf * 8 + (lane & 7);
                ldsm2(b[nf][0], b[nf][1],
                      bBase + row * 80 + (ks * 16 + ((lane >> 3) & 1) * 8) * 2);
            }
#pragma unroll
            for (int mf = 0; mf < 4; mf++)
#pragma unroll
                for (int nf = 0; nf < 4; nf++)
                    mma16816(acc[mf][nf], a[mf], b[nf]);
        }
        __syncthreads();
    }

#pragma unroll
    for (int mf = 0; mf < 4; mf++) {
        int r = m0 + wm * 64 + mf * 16 + (lane >> 2);
#pragma unroll
        for (int nf = 0; nf < 4; nf++) {
            int c = n0 + wn * 32 + nf * 8 + 2 * (lane & 3);
            float b0 = g_bi[c], b1 = g_bi[c + 1];
            float2 v0 = {acc[mf][nf][0] + b0, acc[mf][nf][1] + b1};
            float2 v1 = {acc[mf][nf][2] + b0, acc[mf][nf][3] + b1};
            *(float2*)&g_XWx[(size_t)r * G4 + c] = v0;
            *(float2*)&g_XWx[(size_t)(r + 8) * G4 + c] = v1;
        }
    }
}

// ---------------- LSTM step: bf16 MMA + fused gates ----------------
__global__ void __launch_bounds__(256)
lstm_mma_step(const __nv_bfloat16* __restrict__ Aptr, int rowStride, int t) {
    __shared__ __align__(16) __nv_bfloat16 As[2][128][40];
    __shared__ __align__(16) __nv_bfloat16 Bs[2][32][40];
    int tid = threadIdx.x;
    int lane = tid & 31, wid = tid >> 5;
    int wm = wid >> 2, wn = wid & 3;
    int n0 = blockIdx.x * 32;

    float acc[4][4];
#pragma unroll
    for (int a = 0; a < 4; a++)
#pragma unroll
        for (int c = 0; c < 4; c++) acc[a][c] = 0.f;

    auto loadA = [&](int s, int k0) {
#pragma unroll
        for (int l = 0; l < 2; l++) {
            int idx = tid + l * 256;
            int row = idx >> 2, ch = idx & 3;
            cp16(&As[s][row][ch * 8], Aptr + (size_t)row * rowStride + k0 + ch * 8);
        }
    };
    auto loadB = [&](int s, int k0) {
        if (tid < 128) {
            int row = tid >> 2, ch = tid & 3;
            cp16(&Bs[s][row][ch * 8], g_WhiT + (size_t)(n0 + row) * HH + k0 + ch * 8);
        }
    };
    loadA(0, 0); loadB(0, 0); cp_commit();

    constexpr int NIT = HH / 32;  // 16
    for (int it = 0; it < NIT; it++) {
        if (it + 1 < NIT) {
            int s = (it + 1) & 1;
            loadA(s, (it + 1) * 32); loadB(s, (it + 1) * 32);
            cp_commit(); cp_wait<1>();
        } else cp_wait<0>();
        __syncthreads();
        int s = it & 1;
        uint32_t aBase = smem_u32(&As[s][0][0]);
        uint32_t bBase = smem_u32(&Bs[s][0][0]);
#pragma unroll
        for (int ks = 0; ks < 2; ks++) {
            uint32_t a[4][4], b[2];
#pragma unroll
            for (int mf = 0; mf < 4; mf++) {
                int row = wm * 64 + mf * 16 + (lane & 15);
                ldsm4(a[mf][0], a[mf][1], a[mf][2], a[mf][3],
                      aBase + row * 80 + (ks * 16 + (lane >> 4) * 8) * 2);
            }
            {
                int row = wn * 8 + (lane & 7);
                ldsm2(b[0], b[1],
                      bBase + row * 80 + (ks * 16 + ((lane >> 3) & 1) * 8) * 2);
            }
#pragma unroll
            for (int mf = 0; mf < 4; mf++)
                mma16816(acc[mf], a[mf], b);
        }
        __syncthreads();
    }

    int cbase = n0 + wn * 8 + 2 * (lane & 3);
    int j = cbase >> 2;
#pragma unroll
    for (int mf = 0; mf < 4; mf++) {
        int r = wm * 64 + mf * 16 + (lane >> 2);
        float2 x0 = *(const float2*)&g_XWx[(size_t)((r << 5) + t) * G4 + cbase];
        float2 x1 = *(const float2*)&g_XWx[(size_t)(((r + 8) << 5) + t) * G4 + cbase];
        float v0 = acc[mf][0] + x0.x, v1 = acc[mf][1] + x0.y;
        float v2 = acc[mf][2] + x1.x, v3 = acc[mf][3] + x1.y;
        float e0 = __shfl_xor_sync(0xffffffffu, v0, 1);
        float e1 = __shfl_xor_sync(0xffffffffu, v1, 1);
        float e2 = __shfl_xor_sync(0xffffffffu, v2, 1);
        float e3 = __shfl_xor_sync(0xffffffffu, v3, 1);
        if (!(lane & 1)) {
            {
                float i_ = sigmoidf_(v0), f_ = sigmoidf_(v1);
                float o_ = sigmoidf_(e0), gg = tanhf(e1);
                float cp = t ? g_c[r * HH + j] : 0.f;
                float cn = f_ * cp + i_ * gg;
                g_c[r * HH + j] = cn;
                g_hb[(size_t)((r << 5) + t) * HH + j] = __float2bfloat16(o_ * tanhf(cn));
            }
            {
                int r8 = r + 8;
                float i_ = sigmoidf_(v2), f_ = sigmoidf_(v3);
                float o_ = sigmoidf_(e2), gg = tanhf(e3);
                float cp = t ? g_c[r8 * HH + j] : 0.f;
                float cn = f_ * cp + i_ * gg;
                g_c[r8 * HH + j] = cn;
                g_hb[(size_t)((r8 << 5) + t) * HH + j] = __float2bfloat16(o_ * tanhf(cn));
            }
        }
    }
}

// ---------------- vocab bf16 MMA GEMM (128x256 block, 64x64 warp tiles) -----
// Dynamic smem (62KB): As | Bs | sred. Per warp-iter: 64 HMMA vs 16 ldsm4.
__global__ void __launch_bounds__(256, 1)
vocab_mma_kernel(const float* __restrict__ bv) {
    extern __shared__ __align__(16) char vsm[];
    __nv_bfloat16 (*As)[VBM][40] = (__nv_bfloat16 (*)[VBM][40])vsm;
    __nv_bfloat16 (*Bs)[VBN][40] = (__nv_bfloat16 (*)[VBN][40])(vsm + VAS_B);
    float (*sred)[VBM] = (float (*)[VBM])(vsm + VAS_B + VBS_B);

    int tid = threadIdx.x;
    int lane = tid & 31, wid = tid >> 5;
    int wm = wid & 1, wn = wid >> 1;          // 2x4 warp grid: 64 rows x 64 cols each
    int m0 = blockIdx.x * VBM;
    int n0 = blockIdx.y * VBN;

    float acc[4][8][4];
#pragma unroll
    for (int a = 0; a < 4; a++)
#pragma unroll
        for (int b = 0; b < 8; b++)
#pragma unroll
            for (int c = 0; c < 4; c++) acc[a][b][c] = 0.f;

    auto loadA = [&](int s, int k0) {
#pragma unroll
        for (int l = 0; l < 2; l++) {
            int idx = tid + l * 256;
            int row = idx >> 2, ch = idx & 3;
            cp16(&As[s][row][ch * 8], g_hb + (size_t)(m0 + row) * HH + k0 + ch * 8);
        }
    };
    auto loadB = [&](int s, int k0) {
#pragma unroll
        for (int l = 0; l < 4; l++) {
            int idx = tid + l * 256;
            int row = idx >> 2, ch = idx & 3;
            cp16(&Bs[s][row][ch * 8], g_wt + (size_t)(n0 + row) * HH + k0 + ch * 8);
        }
    };
    loadA(0, 0); loadB(0, 0); cp_commit();

    constexpr int NIT = HH / 32;  // 16
    for (int it = 0; it < NIT; it++) {
        if (it + 1 < NIT) {
            int s = (it + 1) & 1;
            loadA(s, (it + 1) * 32); loadB(s, (it + 1) * 32);
            cp_commit(); cp_wait<1>();
        } else cp_wait<0>();
        __syncthreads();
        int s = it & 1;
        uint32_t aBase = smem_u32(&As[s][0][0]);
        uint32_t bBase = smem_u32(&Bs[s][0][0]);
#pragma unroll
        for (int ks = 0; ks < 2; ks++) {
            uint32_t a[4][4], b[8][2];
#pragma unroll
            for (int mf = 0; mf < 4; mf++) {
                int row = wm * 64 + mf * 16 + (lane & 15);
                ldsm4(a[mf][0], a[mf][1], a[mf][2], a[mf][3],
                      aBase + row * 80 + (ks * 16 + (lane >> 4) * 8) * 2);
            }
            // B via x4: matrices (nf=2p,kh0),(2p,kh1),(2p+1,kh0),(2p+1,kh1)
#pragma unroll
            for (int p = 0; p < 4; p++) {
                int mI = lane >> 3;                     // 0..3
                int nf_loc = 2 * p + (mI >> 1);
                int kh = mI & 1;
                int row = wn * 64 + nf_loc * 8 + (lane & 7);
                ldsm4(b[2 * p][0], b[2 * p][1], b[2 * p + 1][0], b[2 * p + 1][1],
                      bBase + row * 80 + (ks * 16 + kh * 8) * 2);
            }
#pragma unroll
            for (int mf = 0; mf < 4; mf++)
#pragma unroll
                for (int nf = 0; nf < 8; nf++)
                    mma16816(acc[mf][nf], a[mf], b[nf]);
        }
        __syncthreads();
    }

    // epilogue: exp(score + bias) row sums (scores bounded: |h|<1, Var<=1)
    float rowsum[4][2] = {};
#pragma unroll
    for (int nf = 0; nf < 8; nf++) {
        int nb_ = n0 + wn * 64 + nf * 8 + 2 * (lane & 3);
        float b0 = bv[nb_], b1 = bv[nb_ + 1];
#pragma unroll
        for (int mf = 0; mf < 4; mf++) {
            rowsum[mf][0] += __expf(acc[mf][nf][0] + b0) + __expf(acc[mf][nf][1] + b1);
            rowsum[mf][1] += __expf(acc[mf][nf][2] + b0) + __expf(acc[mf][nf][3] + b1);
        }
    }
#pragma unroll
    for (int mf = 0; mf < 4; mf++)
#pragma unroll
        for (int h = 0; h < 2; h++) {
            rowsum[mf][h] += __shfl_xor_sync(0xffffffffu, rowsum[mf][h], 1);
            rowsum[mf][h] += __shfl_xor_sync(0xffffffffu, rowsum[mf][h], 2);
        }
    if ((lane & 3) == 0) {
#pragma unroll
        for (int mf = 0; mf < 4; mf++) {
            int r = wm * 64 + mf * 16 + (lane >> 2);
            sred[wn][r]     = rowsum[mf][0];
            sred[wn][r + 8] = rowsum[mf][1];
        }
    }
    __syncthreads();
    if (tid < VBM) {
        float s = sred[0][tid] + sred[1][tid] + sred[2][tid] + sred[3][tid];
        g_part[(size_t)(m0 + tid) * NTILES_V + blockIdx.y] = s;
    }
}

// ---------------- target scores (coalesced bf16) ----------------
__global__ void tscore_kernel(const float* __restrict__ bv) {
    int w = (blockIdx.x * blockDim.x + threadIdx.x) >> 5;
    int lane = threadIdx.x & 31;
    if (w >= M_NT) return;
    int tgt = g_tgt[w];
    const uint4* h4 = (const uint4*)(g_hb + (size_t)w * HH);
    const uint4* w4 = (const uint4*)(g_wt + (size_t)tgt * HH);
    float s = 0.f;
#pragma unroll
    for (int i = 0; i < 2; i++) {
        uint4 a = h4[lane + i * 32];
        uint4 b = w4[lane + i * 32];
        const uint32_t* ap = &a.x;
        const uint32_t* bp = &b.x;
#pragma unroll
        for (int q = 0; q < 4; q++) {
            float2 fa = __bfloat1622float2(*(const __nv_bfloat162*)&ap[q]);
            float2 fb = __bfloat1622float2(*(const __nv_bfloat162*)&bp[q]);
            s += fa.x * fb.x + fa.y * fb.y;
        }
    }
#pragma unroll
    for (int off = 16; off; off >>= 1) s += __shfl_down_sync(0xffffffffu, s, off);
    if (lane == 0) g_tsc[w] = s + bv[tgt];
}

// ---------------- per-token nll + final loss ----------------
__global__ void nll_kernel() {
    int w = (blockIdx.x * blockDim.x + threadIdx.x) >> 5;
    int lane = threadIdx.x & 31;
    if (w >= M_NT) return;
    const float* p = g_part + (size_t)w * NTILES_V;
    float s = 0.f;
    for (int i = lane; i < NTILES_V; i += 32) s += p[i];
#pragma unroll
    for (int off = 16; off; off >>= 1) s += __shfl_down_sync(0xffffffffu, s, off);
    if (lane == 0)
        g_nll[w] = (g_tgt[w] != 0) ? (logf(s) - g_tsc[w]) : 0.f;
}

__global__ void loss_kernel(float* __restrict__ out) {
    __shared__ float sm[256];
    float s = 0.f;
    for (int i = threadIdx.x; i < M_NT; i += 256) s += g_nll[i];
    sm[threadIdx.x] = s;
    __syncthreads();
    for (int off = 128; off; off >>= 1) {
        if (threadIdx.x < off) sm[threadIdx.x] += sm[threadIdx.x + off];
        __syncthreads();
    }
    if (threadIdx.x == 0) out[0] = sm[0] / (float)NB;
}

// ---------------- launch ----------------
extern "C" void kernel_launch(void* const* d_in, const int* in_sizes, int n_in,
                              void* d_out, int out_size) {
    const float* features = (const float*)d_in[0];
    const void*  captions =               d_in[1];
    const float* W_proj   = (const float*)d_in[2];
    const float* b_proj   = (const float*)d_in[3];
    const float* W_embed  = (const float*)d_in[4];
    const float* Wx       = (const float*)d_in[5];
    const float* Wh       = (const float*)d_in[6];
    const float* bb       = (const float*)d_in[7];
    const float* W_vocab  = (const float*)d_in[8];
    const float* b_vocab  = (const float*)d_in[9];
    float* out = (float*)d_out;

    float *p_h0, *p_bi;
    __nv_bfloat16 *p_WxiT, *p_WhiT, *p_h0b, *p_hb;
    cudaGetSymbolAddress((void**)&p_h0,   g_h0);
    cudaGetSymbolAddress((void**)&p_bi,   g_bi);
    cudaGetSymbolAddress((void**)&p_WxiT, g_WxiT);
    cudaGetSymbolAddress((void**)&p_WhiT, g_WhiT);
    cudaGetSymbolAddress((void**)&p_h0b,  g_h0b);
    cudaGetSymbolAddress((void**)&p_hb,   g_hb);

    cudaFuncSetAttribute(vocab_mma_kernel,
                         cudaFuncAttributeMaxDynamicSharedMemorySize, VSMEM);

    // 0. indices + weight conversions
    detect_kernel<<<1, 256>>>((const unsigned int*)captions);
    build_idx_kernel<<<(M_NT + 255) / 256, 256>>>(captions);
    reorder_bias_kernel<<<(G4 + 255) / 256, 256>>>(bb, p_bi);
    transT_gate_kernel<<<dim3(G4 / 32, WD / 32), dim3(32, 8)>>>(Wx, p_WxiT, WD);
    transT_gate_kernel<<<dim3(G4 / 32, HH / 32), dim3(32, 8)>>>(Wh, p_WhiT, HH);
    convW_kernel<<<dim3(VV / 32, HH / 32), dim3(32, 8)>>>(W_vocab);
    gatherconv_kernel<<<(M_NT * WD + 255) / 256, 256>>>(W_embed);

    // 1. h0
    sgemm_k<32, 64, 16, 2, 4><<<dim3(HH / 64, NB / 32), 256>>>(
        features, DF, W_proj, HH, p_h0, HH, b_proj, DF);
    convh0_kernel<<<(NB * HH + 255) / 256, 256>>>();

    // 2. XWx
    xwx_mma_kernel<<<dim3(M_NT / 128, G4 / 128), 256>>>();

    // 3. LSTM
    for (int t = 0; t < TT; t++) {
        const __nv_bfloat16* Aptr = (t == 0) ? p_h0b : (p_hb + (size_t)(t - 1) * HH);
        int stride = (t == 0) ? HH : (TT * HH);
        lstm_mma_step<<<G4 / 32, 256>>>(Aptr, stride, t);
    }

    // 4. vocab bf16 MMA GEMM + fused sum-exp (128x256 blocks, dynamic smem)
    vocab_mma_kernel<<<dim3(M_NT / VBM, NTILES_V), 256, VSMEM>>>(b_vocab);

    // 5. target scores, per-token nll, final loss
    tscore_kernel<<<M_NT / 4, 128>>>(b_vocab);
    nll_kernel<<<M_NT / 4, 128>>>();
    loss_kernel<<<1, 256>>>(out);
}

// round 8
// speedup vs baseline: 1.3098x; 1.2706x over previous
#include <cuda_runtime.h>
#include <cuda_bf16.h>
#include <math.h>
#include <stdint.h>

// Problem constants
#define NB   128
#define TT   32
#define NTOK (128*33)
#define DF   1280
#define WD   256
#define HH   512
#define VV   32000
#define M_NT (NB*TT)      // 4096
#define G4   2048
#define VBM  128
#define VBN  128
#define NTILES_V (VV/VBN) // 250
#define HSC  127.0f       // int8 scale for h (|h|<1)
#define WSC  448.0f       // int8 scale for W_vocab (clamped)

// ---------------- device scratch ----------------
__device__ __nv_bfloat16 g_hb[(size_t)M_NT * HH];    // h_all bf16 (tscore path)
__device__ signed char   g_h8[(size_t)M_NT * HH];    // h_all int8 (x127)
__device__ __nv_bfloat16 g_wt[(size_t)VV * HH];      // W_vocab bf16 [n][k]
__device__ signed char   g_w8[(size_t)VV * HH];      // W_vocab int8 [n][k] (x448)
__device__ __nv_bfloat16 g_WxiT[(size_t)G4 * WD];    // gate-interleaved Wx, [n][k] bf16
__device__ __nv_bfloat16 g_WhiT[(size_t)G4 * HH];    // gate-interleaved Wh, [n][k] bf16
__device__ __nv_bfloat16 g_xg[(size_t)M_NT * WD];    // gathered embeddings bf16
__device__ float g_XWx[(size_t)M_NT * G4];           // gate-interleaved x@Wx + b
__device__ float g_h0[NB * HH];
__device__ __nv_bfloat16 g_h0b[NB * HH];
__device__ float g_c[NB * HH];
__device__ float g_bi[G4];
__device__ float g_part[(size_t)M_NT * NTILES_V];
__device__ float g_tsc[M_NT];
__device__ float g_nll[M_NT];
__device__ int   g_rows[M_NT];
__device__ int   g_tgt[M_NT];
__device__ int   g_is64;

// ---------------- small helpers ----------------
__device__ __forceinline__ float sigmoidf_(float x) { return 1.f / (1.f + __expf(-x)); }
__device__ __forceinline__ uint32_t smem_u32(const void* p) {
    return (uint32_t)__cvta_generic_to_shared(p);
}
__device__ __forceinline__ void cp16(void* dst, const void* src) {
    asm volatile("cp.async.cg.shared.global [%0], [%1], 16;"
                 :: "r"(smem_u32(dst)), "l"(src));
}
__device__ __forceinline__ void cp_commit() { asm volatile("cp.async.commit_group;"); }
template<int N> __device__ __forceinline__ void cp_wait() {
    asm volatile("cp.async.wait_group %0;" :: "n"(N));
}
__device__ __forceinline__ void ldsm4(uint32_t& r0, uint32_t& r1, uint32_t& r2, uint32_t& r3, uint32_t addr) {
    asm volatile("ldmatrix.sync.aligned.m8n8.x4.shared.b16 {%0,%1,%2,%3}, [%4];"
                 : "=r"(r0), "=r"(r1), "=r"(r2), "=r"(r3) : "r"(addr));
}
__device__ __forceinline__ void ldsm2(uint32_t& r0, uint32_t& r1, uint32_t addr) {
    asm volatile("ldmatrix.sync.aligned.m8n8.x2.shared.b16 {%0,%1}, [%2];"
                 : "=r"(r0), "=r"(r1) : "r"(addr));
}
__device__ __forceinline__ void mma16816(float* c, const uint32_t* a, const uint32_t* b) {
    asm volatile("mma.sync.aligned.m16n8k16.row.col.f32.bf16.bf16.f32 "
                 "{%0,%1,%2,%3}, {%4,%5,%6,%7}, {%8,%9}, {%0,%1,%2,%3};"
                 : "+f"(c[0]), "+f"(c[1]), "+f"(c[2]), "+f"(c[3])
                 : "r"(a[0]), "r"(a[1]), "r"(a[2]), "r"(a[3]), "r"(b[0]), "r"(b[1]));
}
__device__ __forceinline__ void mma16832s8(int* c, const uint32_t* a, const uint32_t* b) {
    asm volatile("mma.sync.aligned.m16n8k32.row.col.s32.s8.s8.s32 "
                 "{%0,%1,%2,%3}, {%4,%5,%6,%7}, {%8,%9}, {%0,%1,%2,%3};"
                 : "+r"(c[0]), "+r"(c[1]), "+r"(c[2]), "+r"(c[3])
                 : "r"(a[0]), "r"(a[1]), "r"(a[2]), "r"(a[3]), "r"(b[0]), "r"(b[1]));
}
__device__ __forceinline__ signed char q8h(float x) {     // |x|<1
    return (signed char)__float2int_rn(x * HSC);
}
__device__ __forceinline__ signed char q8w(float x) {
    int v = __float2int_rn(x * WSC);
    v = v > 127 ? 127 : (v < -127 ? -127 : v);
    return (signed char)v;
}

// ---------------- caption dtype detection + index build ----------------
__global__ void detect_kernel(const unsigned int* __restrict__ w) {
    __shared__ int found;
    if (threadIdx.x == 0) found = 0;
    __syncthreads();
    for (int i = threadIdx.x; i < NTOK / 2; i += blockDim.x)
        if (w[2 * i + 1] != 0u) found = 1;
    __syncthreads();
    if (threadIdx.x == 0) g_is64 = (found == 0) ? 1 : 0;
}

__global__ void build_idx_kernel(const void* __restrict__ caps) {
    int m = blockIdx.x * blockDim.x + threadIdx.x;
    if (m >= M_NT) return;
    int n = m >> 5, t = m & 31;
    int ci, co;
    if (g_is64) {
        const long long* c = (const long long*)caps;
        ci = (int)c[n * 33 + t];  co = (int)c[n * 33 + t + 1];
    } else {
        const int* c = (const int*)caps;
        ci = c[n * 33 + t];       co = c[n * 33 + t + 1];
    }
    g_rows[m] = ci;  g_tgt[m] = co;
}

// ---------------- bias gate-interleave ----------------
__global__ void reorder_bias_kernel(const float* __restrict__ in, float* __restrict__ out) {
    int np = blockIdx.x * blockDim.x + threadIdx.x;
    if (np >= G4) return;
    int j = np >> 2, g = np & 3;
    out[np] = in[g * HH + j];
}

// ---- transpose + gate-interleave + bf16: out[(j*4+g)][k] = in[k][g*512+j] --
__global__ void transT_gate_kernel(const float* __restrict__ in, __nv_bfloat16* __restrict__ out, int K) {
    __shared__ float tile[32][33];
    int np0 = blockIdx.x * 32, k0 = blockIdx.y * 32;
    int tx = threadIdx.x, ty = threadIdx.y;  // 32 x 8
#pragma unroll
    for (int r = 0; r < 4; r++)
        tile[ty + r * 8][tx] = in[(size_t)(k0 + ty + r * 8) * G4 + np0 + tx];
    __syncthreads();
#pragma unroll
    for (int r = 0; r < 4; r++) {
        int npl = ty + r * 8;
        int np = np0 + npl;
        int g = np >> 9, j = np & 511;
        int n = (j << 2) + g;
        out[(size_t)n * K + k0 + tx] = __float2bfloat16(tile[tx][npl]);
    }
}

// ---- W_vocab fp32 [k][n] -> bf16 [n][k] + int8 [n][k] ----------------------
__global__ void convW_kernel(const float* __restrict__ Wv) {
    __shared__ float tile[32][33];
    int n0 = blockIdx.x * 32, k0 = blockIdx.y * 32;
    int tx = threadIdx.x, ty = threadIdx.y;
#pragma unroll
    for (int r = 0; r < 4; r++)
        tile[ty + r * 8][tx] = Wv[(size_t)(k0 + ty + r * 8) * VV + n0 + tx];
    __syncthreads();
#pragma unroll
    for (int r = 0; r < 4; r++) {
        int n = ty + r * 8;
        float w = tile[tx][n];
        g_wt[(size_t)(n0 + n) * HH + k0 + tx] = __float2bfloat16(w);
        g_w8[(size_t)(n0 + n) * HH + k0 + tx] = q8w(w);
    }
}

// ---- gather + convert embeddings ----
__global__ void gatherconv_kernel(const float* __restrict__ We) {
    int idx = blockIdx.x * blockDim.x + threadIdx.x;
    if (idx >= M_NT * WD) return;
    int m = idx >> 8, k = idx & (WD - 1);
    g_xg[idx] = __float2bfloat16(We[(size_t)g_rows[m] * WD + k]);
}

__global__ void convh0_kernel() {
    int i = blockIdx.x * blockDim.x + threadIdx.x;
    if (i < NB * HH) g_h0b[i] = __float2bfloat16(g_h0[i]);
}

// ---------------- fp32 SGEMM (h0 only) ----------------
template<int BM, int BN, int BK, int TM, int TN>
__global__ void __launch_bounds__(256)
sgemm_k(const float* __restrict__ A, int lda,
        const float* __restrict__ B, int ldb,
        float* __restrict__ C, int ldc,
        const float* __restrict__ bias, int K)
{
    constexpr int THREADS = (BM / TM) * (BN / TN);
    constexpr int ALOAD = BM * BK / THREADS;
    constexpr int BLOAD = BK * BN / THREADS;
    __shared__ float As[BK][BM + 1];
    __shared__ float Bs[BK][BN];
    const int tid = threadIdx.x;
    const int tx = tid % (BN / TN);
    const int ty = tid / (BN / TN);
    const int m0 = blockIdx.y * BM;
    const int n0 = blockIdx.x * BN;

    float acc[TM][TN];
#pragma unroll
    for (int i = 0; i < TM; i++)
#pragma unroll
        for (int j = 0; j < TN; j++) acc[i][j] = 0.f;

    for (int k0 = 0; k0 < K; k0 += BK) {
#pragma unroll
        for (int l = 0; l < ALOAD; l++) {
            int idx = tid + l * THREADS;
            int k = idx % BK, m = idx / BK;
            As[k][m] = A[(size_t)(m0 + m) * lda + k0 + k];
        }
#pragma unroll
        for (int l = 0; l < BLOAD; l++) {
            int idx = tid + l * THREADS;
            int n = idx % BN, k = idx / BN;
            Bs[k][n] = B[(size_t)(k0 + k) * ldb + n0 + n];
        }
        __syncthreads();
#pragma unroll
        for (int kk = 0; kk < BK; kk++) {
            float a[TM], b[TN];
#pragma unroll
            for (int i = 0; i < TM; i++) a[i] = As[kk][ty * TM + i];
#pragma unroll
            for (int j = 0; j < TN; j++) b[j] = Bs[kk][tx * TN + j];
#pragma unroll
            for (int i = 0; i < TM; i++)
#pragma unroll
                for (int j = 0; j < TN; j++) acc[i][j] += a[i] * b[j];
        }
        __syncthreads();
    }
#pragma unroll
    for (int i = 0; i < TM; i++)
#pragma unroll
        for (int j = 0; j < TN; j++) {
            int n = n0 + tx * TN + j;
            C[(size_t)(m0 + ty * TM + i) * ldc + n] = acc[i][j] + bias[n];
        }
}

// ---------------- XWx bf16 MMA ----------------
__global__ void __launch_bounds__(256)
xwx_mma_kernel() {
    __shared__ __align__(16) __nv_bfloat16 As[2][128][40];
    __shared__ __align__(16) __nv_bfloat16 Bs[2][128][40];
    int tid = threadIdx.x;
    int lane = tid & 31, wid = tid >> 5;
    int wm = wid & 1, wn = wid >> 1;
    int m0 = blockIdx.x * 128;
    int n0 = blockIdx.y * 128;

    float acc[4][4][4];
#pragma unroll
    for (int a = 0; a < 4; a++)
#pragma unroll
        for (int b = 0; b < 4; b++)
#pragma unroll
            for (int c = 0; c < 4; c++) acc[a][b][c] = 0.f;

    auto loadA = [&](int s, int k0) {
#pragma unroll
        for (int l = 0; l < 2; l++) {
            int idx = tid + l * 256;
            int row = idx >> 2, ch = idx & 3;
            cp16(&As[s][row][ch * 8], g_xg + (size_t)(m0 + row) * WD + k0 + ch * 8);
        }
    };
    auto loadB = [&](int s, int k0) {
#pragma unroll
        for (int l = 0; l < 2; l++) {
            int idx = tid + l * 256;
            int row = idx >> 2, ch = idx & 3;
            cp16(&Bs[s][row][ch * 8], g_WxiT + (size_t)(n0 + row) * WD + k0 + ch * 8);
        }
    };
    loadA(0, 0); loadB(0, 0); cp_commit();

    constexpr int NIT = WD / 32;  // 8
    for (int it = 0; it < NIT; it++) {
        if (it + 1 < NIT) {
            int s = (it + 1) & 1;
            loadA(s, (it + 1) * 32); loadB(s, (it + 1) * 32);
            cp_commit(); cp_wait<1>();
        } else cp_wait<0>();
        __syncthreads();
        int s = it & 1;
        uint32_t aBase = smem_u32(&As[s][0][0]);
        uint32_t bBase = smem_u32(&Bs[s][0][0]);
#pragma unroll
        for (int ks = 0; ks < 2; ks++) {
            uint32_t a[4][4], b[4][2];
#pragma unroll
            for (int mf = 0; mf < 4; mf++) {
                int row = wm * 64 + mf * 16 + (lane & 15);
                ldsm4(a[mf][0], a[mf][1], a[mf][2], a[mf][3],
                      aBase + row * 80 + (ks * 16 + (lane >> 4) * 8) * 2);
            }
#pragma unroll
            for (int nf = 0; nf < 4; nf++) {
                int row = wn * 32 + nf * 8 + (lane & 7);
                ldsm2(b[nf][0], b[nf][1],
                      bBase + row * 80 + (ks * 16 + ((lane >> 3) & 1) * 8) * 2);
            }
#pragma unroll
            for (int mf = 0; mf < 4; mf++)
#pragma unroll
                for (int nf = 0; nf < 4; nf++)
                    mma16816(acc[mf][nf], a[mf], b[nf]);
        }
        __syncthreads();
    }

#pragma unroll
    for (int mf = 0; mf < 4; mf++) {
        int r = m0 + wm * 64 + mf * 16 + (lane >> 2);
#pragma unroll
        for (int nf = 0; nf < 4; nf++) {
            int c = n0 + wn * 32 + nf * 8 + 2 * (lane & 3);
            float b0 = g_bi[c], b1 = g_bi[c + 1];
            float2 v0 = {acc[mf][nf][0] + b0, acc[mf][nf][1] + b1};
            float2 v1 = {acc[mf][nf][2] + b0, acc[mf][nf][3] + b1};
            *(float2*)&g_XWx[(size_t)r * G4 + c] = v0;
            *(float2*)&g_XWx[(size_t)(r + 8) * G4 + c] = v1;
        }
    }
}

// ---------------- LSTM step: bf16 MMA + fused gates ----------------
__global__ void __launch_bounds__(256)
lstm_mma_step(const __nv_bfloat16* __restrict__ Aptr, int rowStride, int t) {
    __shared__ __align__(16) __nv_bfloat16 As[2][128][40];
    __shared__ __align__(16) __nv_bfloat16 Bs[2][32][40];
    int tid = threadIdx.x;
    int lane = tid & 31, wid = tid >> 5;
    int wm = wid >> 2, wn = wid & 3;
    int n0 = blockIdx.x * 32;

    float acc[4][4];
#pragma unroll
    for (int a = 0; a < 4; a++)
#pragma unroll
        for (int c = 0; c < 4; c++) acc[a][c] = 0.f;

    auto loadA = [&](int s, int k0) {
#pragma unroll
        for (int l = 0; l < 2; l++) {
            int idx = tid + l * 256;
            int row = idx >> 2, ch = idx & 3;
            cp16(&As[s][row][ch * 8], Aptr + (size_t)row * rowStride + k0 + ch * 8);
        }
    };
    auto loadB = [&](int s, int k0) {
        if (tid < 128) {
            int row = tid >> 2, ch = tid & 3;
            cp16(&Bs[s][row][ch * 8], g_WhiT + (size_t)(n0 + row) * HH + k0 + ch * 8);
        }
    };
    loadA(0, 0); loadB(0, 0); cp_commit();

    constexpr int NIT = HH / 32;  // 16
    for (int it = 0; it < NIT; it++) {
        if (it + 1 < NIT) {
            int s = (it + 1) & 1;
            loadA(s, (it + 1) * 32); loadB(s, (it + 1) * 32);
            cp_commit(); cp_wait<1>();
        } else cp_wait<0>();
        __syncthreads();
        int s = it & 1;
        uint32_t aBase = smem_u32(&As[s][0][0]);
        uint32_t bBase = smem_u32(&Bs[s][0][0]);
#pragma unroll
        for (int ks = 0; ks < 2; ks++) {
            uint32_t a[4][4], b[2];
#pragma unroll
            for (int mf = 0; mf < 4; mf++) {
                int row = wm * 64 + mf * 16 + (lane & 15);
                ldsm4(a[mf][0], a[mf][1], a[mf][2], a[mf][3],
                      aBase + row * 80 + (ks * 16 + (lane >> 4) * 8) * 2);
            }
            {
                int row = wn * 8 + (lane & 7);
                ldsm2(b[0], b[1],
                      bBase + row * 80 + (ks * 16 + ((lane >> 3) & 1) * 8) * 2);
            }
#pragma unroll
            for (int mf = 0; mf < 4; mf++)
                mma16816(acc[mf], a[mf], b);
        }
        __syncthreads();
    }

    int cbase = n0 + wn * 8 + 2 * (lane & 3);
    int j = cbase >> 2;
#pragma unroll
    for (int mf = 0; mf < 4; mf++) {
        int r = wm * 64 + mf * 16 + (lane >> 2);
        float2 x0 = *(const float2*)&g_XWx[(size_t)((r << 5) + t) * G4 + cbase];
        float2 x1 = *(const float2*)&g_XWx[(size_t)(((r + 8) << 5) + t) * G4 + cbase];
        float v0 = acc[mf][0] + x0.x, v1 = acc[mf][1] + x0.y;
        float v2 = acc[mf][2] + x1.x, v3 = acc[mf][3] + x1.y;
        float e0 = __shfl_xor_sync(0xffffffffu, v0, 1);
        float e1 = __shfl_xor_sync(0xffffffffu, v1, 1);
        float e2 = __shfl_xor_sync(0xffffffffu, v2, 1);
        float e3 = __shfl_xor_sync(0xffffffffu, v3, 1);
        if (!(lane & 1)) {
            {
                float i_ = sigmoidf_(v0), f_ = sigmoidf_(v1);
                float o_ = sigmoidf_(e0), gg = tanhf(e1);
                float cp = t ? g_c[r * HH + j] : 0.f;
                float cn = f_ * cp + i_ * gg;
                float hv = o_ * tanhf(cn);
                g_c[r * HH + j] = cn;
                size_t hi = (size_t)((r << 5) + t) * HH + j;
                g_hb[hi] = __float2bfloat16(hv);
                g_h8[hi] = q8h(hv);
            }
            {
                int r8 = r + 8;
                float i_ = sigmoidf_(v2), f_ = sigmoidf_(v3);
                float o_ = sigmoidf_(e2), gg = tanhf(e3);
                float cp = t ? g_c[r8 * HH + j] : 0.f;
                float cn = f_ * cp + i_ * gg;
                float hv = o_ * tanhf(cn);
                g_c[r8 * HH + j] = cn;
                size_t hi = (size_t)((r8 << 5) + t) * HH + j;
                g_hb[hi] = __float2bfloat16(hv);
                g_h8[hi] = q8h(hv);
            }
        }
    }
}

// ---------------- vocab INT8 MMA GEMM + fused sum-exp epilogue --------------
// Block 128x128, K=512 in 8 chunks of 64 int8 (64B rows, 80B padded).
// s8 k32 fragment layout identical to e4m3 k32 / bf16 k16 addressing scheme.
__global__ void __launch_bounds__(256)
vocab_s8_kernel(const float* __restrict__ bv) {
    __shared__ __align__(16) uint8_t As[2][VBM][80];
    __shared__ __align__(16) uint8_t Bs[2][VBN][80];
    __shared__ float sred[4][VBM];
    int tid = threadIdx.x;
    int lane = tid & 31, wid = tid >> 5;
    int wm = wid & 1, wn = wid >> 1;          // warp tile 64m x 32n
    int m0 = blockIdx.x * VBM;
    int n0 = blockIdx.y * VBN;

    int acc[4][4][4];
#pragma unroll
    for (int a = 0; a < 4; a++)
#pragma unroll
        for (int b = 0; b < 4; b++)
#pragma unroll
            for (int c = 0; c < 4; c++) acc[a][b][c] = 0;

    auto loadA = [&](int s, int k0) {
#pragma unroll
        for (int l = 0; l < 2; l++) {
            int idx = tid + l * 256;
            int row = idx >> 2, ch = idx & 3;
            cp16(&As[s][row][ch * 16], g_h8 + (size_t)(m0 + row) * HH + k0 + ch * 16);
        }
    };
    auto loadB = [&](int s, int k0) {
#pragma unroll
        for (int l = 0; l < 2; l++) {
            int idx = tid + l * 256;
            int row = idx >> 2, ch = idx & 3;
            cp16(&Bs[s][row][ch * 16], g_w8 + (size_t)(n0 + row) * HH + k0 + ch * 16);
        }
    };
    loadA(0, 0); loadB(0, 0); cp_commit();

    constexpr int NIT = HH / 64;  // 8 chunks of 64 int8
    for (int it = 0; it < NIT; it++) {
        if (it + 1 < NIT) {
            int s = (it + 1) & 1;
            loadA(s, (it + 1) * 64); loadB(s, (it + 1) * 64);
            cp_commit(); cp_wait<1>();
        } else cp_wait<0>();
        __syncthreads();
        int s = it & 1;
        uint32_t aBase = smem_u32(&As[s][0][0]);
        uint32_t bBase = smem_u32(&Bs[s][0][0]);
#pragma unroll
        for (int ks = 0; ks < 2; ks++) {         // two k32 mma steps per chunk
            uint32_t a[4][4], b[4][2];
#pragma unroll
            for (int mf = 0; mf < 4; mf++) {
                int row = wm * 64 + mf * 16 + (lane & 15);
                ldsm4(a[mf][0], a[mf][1], a[mf][2], a[mf][3],
                      aBase + row * 80 + ks * 32 + (lane >> 4) * 16);
            }
#pragma unroll
            for (int nf = 0; nf < 4; nf++) {
                int row = wn * 32 + nf * 8 + (lane & 7);
                ldsm2(b[nf][0], b[nf][1],
                      bBase + row * 80 + ks * 32 + ((lane >> 3) & 1) * 16);
            }
#pragma unroll
            for (int mf = 0; mf < 4; mf++)
#pragma unroll
                for (int nf = 0; nf < 4; nf++)
                    mma16832s8(acc[mf][nf], a[mf], b[nf]);
        }
        __syncthreads();
    }

    // epilogue: scores = acc/(127*448) + bias; sum exp per row
    const float INV = 1.f / (HSC * WSC);
    float rowsum[4][2] = {};
#pragma unroll
    for (int nf = 0; nf < 4; nf++) {
        int nb_ = n0 + wn * 32 + nf * 8 + 2 * (lane & 3);
        float b0 = bv[nb_], b1 = bv[nb_ + 1];
#pragma unroll
        for (int mf = 0; mf < 4; mf++) {
            rowsum[mf][0] += __expf(fmaf((float)acc[mf][nf][0], INV, b0))
                           + __expf(fmaf((float)acc[mf][nf][1], INV, b1));
            rowsum[mf][1] += __expf(fmaf((float)acc[mf][nf][2], INV, b0))
                           + __expf(fmaf((float)acc[mf][nf][3], INV, b1));
        }
    }
#pragma unroll
    for (int mf = 0; mf < 4; mf++)
#pragma unroll
        for (int h = 0; h < 2; h++) {
            rowsum[mf][h] += __shfl_xor_sync(0xffffffffu, rowsum[mf][h], 1);
            rowsum[mf][h] += __shfl_xor_sync(0xffffffffu, rowsum[mf][h], 2);
        }
    if ((lane & 3) == 0) {
#pragma unroll
        for (int mf = 0; mf < 4; mf++) {
            int r = wm * 64 + mf * 16 + (lane >> 2);
            sred[wn][r]     = rowsum[mf][0];
            sred[wn][r + 8] = rowsum[mf][1];
        }
    }
    __syncthreads();
    if (tid < VBM) {
        float s = sred[0][tid] + sred[1][tid] + sred[2][tid] + sred[3][tid];
        g_part[(size_t)(m0 + tid) * NTILES_V + blockIdx.y] = s;
    }
}

// ---------------- target scores (coalesced bf16) ----------------
__global__ void tscore_kernel(const float* __restrict__ bv) {
    int w = (blockIdx.x * blockDim.x + threadIdx.x) >> 5;
    int lane = threadIdx.x & 31;
    if (w >= M_NT) return;
    int tgt = g_tgt[w];
    const uint4* h4 = (const uint4*)(g_hb + (size_t)w * HH);
    const uint4* w4 = (const uint4*)(g_wt + (size_t)tgt * HH);
    float s = 0.f;
#pragma unroll
    for (int i = 0; i < 2; i++) {
        uint4 a = h4[lane + i * 32];
        uint4 b = w4[lane + i * 32];
        const uint32_t* ap = &a.x;
        const uint32_t* bp = &b.x;
#pragma unroll
        for (int q = 0; q < 4; q++) {
            float2 fa = __bfloat1622float2(*(const __nv_bfloat162*)&ap[q]);
            float2 fb = __bfloat1622float2(*(const __nv_bfloat162*)&bp[q]);
            s += fa.x * fb.x + fa.y * fb.y;
        }
    }
#pragma unroll
    for (int off = 16; off; off >>= 1) s += __shfl_down_sync(0xffffffffu, s, off);
    if (lane == 0) g_tsc[w] = s + bv[tgt];
}

// ---------------- per-token nll + final loss ----------------
__global__ void nll_kernel() {
    int w = (blockIdx.x * blockDim.x + threadIdx.x) >> 5;
    int lane = threadIdx.x & 31;
    if (w >= M_NT) return;
    const float* p = g_part + (size_t)w * NTILES_V;
    float s = 0.f;
    for (int i = lane; i < NTILES_V; i += 32) s += p[i];
#pragma unroll
    for (int off = 16; off; off >>= 1) s += __shfl_down_sync(0xffffffffu, s, off);
    if (lane == 0)
        g_nll[w] = (g_tgt[w] != 0) ? (logf(s) - g_tsc[w]) : 0.f;
}

__global__ void loss_kernel(float* __restrict__ out) {
    __shared__ float sm[256];
    float s = 0.f;
    for (int i = threadIdx.x; i < M_NT; i += 256) s += g_nll[i];
    sm[threadIdx.x] = s;
    __syncthreads();
    for (int off = 128; off; off >>= 1) {
        if (threadIdx.x < off) sm[threadIdx.x] += sm[threadIdx.x + off];
        __syncthreads();
    }
    if (threadIdx.x == 0) out[0] = sm[0] / (float)NB;
}

// ---------------- launch ----------------
extern "C" void kernel_launch(void* const* d_in, const int* in_sizes, int n_in,
                              void* d_out, int out_size) {
    const float* features = (const float*)d_in[0];
    const void*  captions =               d_in[1];
    const float* W_proj   = (const float*)d_in[2];
    const float* b_proj   = (const float*)d_in[3];
    const float* W_embed  = (const float*)d_in[4];
    const float* Wx       = (const float*)d_in[5];
    const float* Wh       = (const float*)d_in[6];
    const float* bb       = (const float*)d_in[7];
    const float* W_vocab  = (const float*)d_in[8];
    const float* b_vocab  = (const float*)d_in[9];
    float* out = (float*)d_out;

    float *p_h0, *p_bi;
    __nv_bfloat16 *p_WxiT, *p_WhiT, *p_h0b, *p_hb;
    cudaGetSymbolAddress((void**)&p_h0,   g_h0);
    cudaGetSymbolAddress((void**)&p_bi,   g_bi);
    cudaGetSymbolAddress((void**)&p_WxiT, g_WxiT);
    cudaGetSymbolAddress((void**)&p_WhiT, g_WhiT);
    cudaGetSymbolAddress((void**)&p_h0b,  g_h0b);
    cudaGetSymbolAddress((void**)&p_hb,   g_hb);

    // 0. indices + weight conversions
    detect_kernel<<<1, 256>>>((const unsigned int*)captions);
    build_idx_kernel<<<(M_NT + 255) / 256, 256>>>(captions);
    reorder_bias_kernel<<<(G4 + 255) / 256, 256>>>(bb, p_bi);
    transT_gate_kernel<<<dim3(G4 / 32, WD / 32), dim3(32, 8)>>>(Wx, p_WxiT, WD);
    transT_gate_kernel<<<dim3(G4 / 32, HH / 32), dim3(32, 8)>>>(Wh, p_WhiT, HH);
    convW_kernel<<<dim3(VV / 32, HH / 32), dim3(32, 8)>>>(W_vocab);
    gatherconv_kernel<<<(M_NT * WD + 255) / 256, 256>>>(W_embed);

    // 1. h0
    sgemm_k<32, 64, 16, 2, 4><<<dim3(HH / 64, NB / 32), 256>>>(
        features, DF, W_proj, HH, p_h0, HH, b_proj, DF);
    convh0_kernel<<<(NB * HH + 255) / 256, 256>>>();

    // 2. XWx
    xwx_mma_kernel<<<dim3(M_NT / 128, G4 / 128), 256>>>();

    // 3. LSTM
    for (int t = 0; t < TT; t++) {
        const __nv_bfloat16* Aptr = (t == 0) ? p_h0b : (p_hb + (size_t)(t - 1) * HH);
        int stride = (t == 0) ? HH : (TT * HH);
        lstm_mma_step<<<G4 / 32, 256>>>(Aptr, stride, t);
    }

    // 4. vocab INT8 MMA GEMM + fused sum-exp
    vocab_s8_kernel<<<dim3(M_NT / VBM, NTILES_V), 256>>>(b_vocab);

    // 5. target scores, per-token nll, final loss
    tscore_kernel<<<M_NT / 4, 128>>>(b_vocab);
    nll_kernel<<<M_NT / 4, 128>>>();
    loss_kernel<<<1, 256>>>(out);
}

// round 9
// speedup vs baseline: 1.4029x; 1.0711x over previous
#include <cuda_runtime.h>
#include <cuda_bf16.h>
#include <math.h>
#include <stdint.h>

// Problem constants
#define NB   128
#define TT   32
#define NTOK (128*33)
#define DF   1280
#define WD   256
#define HH   512
#define VV   32000
#define M_NT (NB*TT)      // 4096
#define G4   2048
#define VBM  128
#define VBN  128
#define NTILES_V (VV/VBN) // 250
#define HSC  127.0f
#define WSC  448.0f
#define NBLK 64           // persistent LSTM blocks

// ---- vocab dynamic smem layout (3-stage): As 3*128*80 | Bs 3*128*80 | sred
#define V_AS_B  (3 * VBM * 80)
#define V_BS_B  (3 * VBN * 80)
#define V_SR_O  (V_AS_B + V_BS_B)
#define V_SMEM  (V_SR_O + 4 * VBM * 4)        // 63488

// ---- persistent LSTM dynamic smem: Bs 32*1040 | As 3*128*80
#define L_BS_B  (32 * 1040)                    // 33280 (odd-granule stride)
#define L_AS_O  L_BS_B
#define L_SMEM  (L_BS_B + 3 * 128 * 80)        // 64000

// ---------------- device scratch ----------------
__device__ __nv_bfloat16 g_hb[(size_t)M_NT * HH];
__device__ signed char   g_h8[(size_t)M_NT * HH];
__device__ __nv_bfloat16 g_wt[(size_t)VV * HH];
__device__ signed char   g_w8[(size_t)VV * HH];
__device__ __nv_bfloat16 g_WxiT[(size_t)G4 * WD];
__device__ __nv_bfloat16 g_WhiT[(size_t)G4 * HH];
__device__ __nv_bfloat16 g_xg[(size_t)M_NT * WD];
__device__ float g_XWx[(size_t)M_NT * G4];
__device__ float g_h0[NB * HH];
__device__ __nv_bfloat16 g_h0b[NB * HH];
__device__ float g_c[NB * HH];
__device__ float g_bi[G4];
__device__ float g_part[(size_t)M_NT * NTILES_V];
__device__ float g_nll[M_NT];
__device__ int   g_rows[M_NT];
__device__ int   g_tgt[M_NT];
__device__ int   g_is64;
__device__ int   g_bar_cnt;
__device__ int   g_bar_phase;

// ---------------- small helpers ----------------
__device__ __forceinline__ float sigmoidf_(float x) { return 1.f / (1.f + __expf(-x)); }
__device__ __forceinline__ uint32_t smem_u32(const void* p) {
    return (uint32_t)__cvta_generic_to_shared(p);
}
__device__ __forceinline__ void cp16(void* dst, const void* src) {
    asm volatile("cp.async.cg.shared.global [%0], [%1], 16;"
                 :: "r"(smem_u32(dst)), "l"(src));
}
__device__ __forceinline__ void cp16a(uint32_t dst, const void* src) {
    asm volatile("cp.async.cg.shared.global [%0], [%1], 16;"
                 :: "r"(dst), "l"(src));
}
__device__ __forceinline__ void cp_commit() { asm volatile("cp.async.commit_group;"); }
template<int N> __device__ __forceinline__ void cp_wait() {
    asm volatile("cp.async.wait_group %0;" :: "n"(N));
}
__device__ __forceinline__ void ldsm4(uint32_t& r0, uint32_t& r1, uint32_t& r2, uint32_t& r3, uint32_t addr) {
    asm volatile("ldmatrix.sync.aligned.m8n8.x4.shared.b16 {%0,%1,%2,%3}, [%4];"
                 : "=r"(r0), "=r"(r1), "=r"(r2), "=r"(r3) : "r"(addr));
}
__device__ __forceinline__ void ldsm2(uint32_t& r0, uint32_t& r1, uint32_t addr) {
    asm volatile("ldmatrix.sync.aligned.m8n8.x2.shared.b16 {%0,%1}, [%2];"
                 : "=r"(r0), "=r"(r1) : "r"(addr));
}
__device__ __forceinline__ void mma16816(float* c, const uint32_t* a, const uint32_t* b) {
    asm volatile("mma.sync.aligned.m16n8k16.row.col.f32.bf16.bf16.f32 "
                 "{%0,%1,%2,%3}, {%4,%5,%6,%7}, {%8,%9}, {%0,%1,%2,%3};"
                 : "+f"(c[0]), "+f"(c[1]), "+f"(c[2]), "+f"(c[3])
                 : "r"(a[0]), "r"(a[1]), "r"(a[2]), "r"(a[3]), "r"(b[0]), "r"(b[1]));
}
__device__ __forceinline__ void mma16832s8(int* c, const uint32_t* a, const uint32_t* b) {
    asm volatile("mma.sync.aligned.m16n8k32.row.col.s32.s8.s8.s32 "
                 "{%0,%1,%2,%3}, {%4,%5,%6,%7}, {%8,%9}, {%0,%1,%2,%3};"
                 : "+r"(c[0]), "+r"(c[1]), "+r"(c[2]), "+r"(c[3])
                 : "r"(a[0]), "r"(a[1]), "r"(a[2]), "r"(a[3]), "r"(b[0]), "r"(b[1]));
}
__device__ __forceinline__ signed char q8h(float x) {
    return (signed char)__float2int_rn(x * HSC);
}
__device__ __forceinline__ signed char q8w(float x) {
    int v = __float2int_rn(x * WSC);
    v = v > 127 ? 127 : (v < -127 ? -127 : v);
    return (signed char)v;
}

// ---------------- caption dtype detection + index build ----------------
__global__ void detect_kernel(const unsigned int* __restrict__ w) {
    __shared__ int found;
    if (threadIdx.x == 0) found = 0;
    __syncthreads();
    for (int i = threadIdx.x; i < NTOK / 2; i += blockDim.x)
        if (w[2 * i + 1] != 0u) found = 1;
    __syncthreads();
    if (threadIdx.x == 0) g_is64 = (found == 0) ? 1 : 0;
}

__global__ void build_idx_kernel(const void* __restrict__ caps) {
    int m = blockIdx.x * blockDim.x + threadIdx.x;
    if (m == 0) { g_bar_cnt = 0; g_bar_phase = 0; }   // reset persistent barrier
    if (m >= M_NT) return;
    int n = m >> 5, t = m & 31;
    int ci, co;
    if (g_is64) {
        const long long* c = (const long long*)caps;
        ci = (int)c[n * 33 + t];  co = (int)c[n * 33 + t + 1];
    } else {
        const int* c = (const int*)caps;
        ci = c[n * 33 + t];       co = c[n * 33 + t + 1];
    }
    g_rows[m] = ci;  g_tgt[m] = co;
}

// ---------------- bias gate-interleave ----------------
__global__ void reorder_bias_kernel(const float* __restrict__ in, float* __restrict__ out) {
    int np = blockIdx.x * blockDim.x + threadIdx.x;
    if (np >= G4) return;
    int j = np >> 2, g = np & 3;
    out[np] = in[g * HH + j];
}

// ---- transpose + gate-interleave + bf16 ----
__global__ void transT_gate_kernel(const float* __restrict__ in, __nv_bfloat16* __restrict__ out, int K) {
    __shared__ float tile[32][33];
    int np0 = blockIdx.x * 32, k0 = blockIdx.y * 32;
    int tx = threadIdx.x, ty = threadIdx.y;  // 32 x 8
#pragma unroll
    for (int r = 0; r < 4; r++)
        tile[ty + r * 8][tx] = in[(size_t)(k0 + ty + r * 8) * G4 + np0 + tx];
    __syncthreads();
#pragma unroll
    for (int r = 0; r < 4; r++) {
        int npl = ty + r * 8;
        int np = np0 + npl;
        int g = np >> 9, j = np & 511;
        int n = (j << 2) + g;
        out[(size_t)n * K + k0 + tx] = __float2bfloat16(tile[tx][npl]);
    }
}

// ---- W_vocab fp32 [k][n] -> bf16 [n][k] + int8 [n][k] ----
__global__ void convW_kernel(const float* __restrict__ Wv) {
    __shared__ float tile[32][33];
    int n0 = blockIdx.x * 32, k0 = blockIdx.y * 32;
    int tx = threadIdx.x, ty = threadIdx.y;
#pragma unroll
    for (int r = 0; r < 4; r++)
        tile[ty + r * 8][tx] = Wv[(size_t)(k0 + ty + r * 8) * VV + n0 + tx];
    __syncthreads();
#pragma unroll
    for (int r = 0; r < 4; r++) {
        int n = ty + r * 8;
        float w = tile[tx][n];
        g_wt[(size_t)(n0 + n) * HH + k0 + tx] = __float2bfloat16(w);
        g_w8[(size_t)(n0 + n) * HH + k0 + tx] = q8w(w);
    }
}

__global__ void gatherconv_kernel(const float* __restrict__ We) {
    int idx = blockIdx.x * blockDim.x + threadIdx.x;
    if (idx >= M_NT * WD) return;
    int m = idx >> 8, k = idx & (WD - 1);
    g_xg[idx] = __float2bfloat16(We[(size_t)g_rows[m] * WD + k]);
}

// ---------------- fp32 SGEMM (h0 only; also emits bf16 copy) ---------------
template<int BM, int BN, int BK, int TM, int TN>
__global__ void __launch_bounds__(256)
sgemm_k(const float* __restrict__ A, int lda,
        const float* __restrict__ B, int ldb,
        float* __restrict__ C, int ldc,
        __nv_bfloat16* __restrict__ Cb,
        const float* __restrict__ bias, int K)
{
    constexpr int THREADS = (BM / TM) * (BN / TN);
    constexpr int ALOAD = BM * BK / THREADS;
    constexpr int BLOAD = BK * BN / THREADS;
    __shared__ float As[BK][BM + 1];
    __shared__ float Bs[BK][BN];
    const int tid = threadIdx.x;
    const int tx = tid % (BN / TN);
    const int ty = tid / (BN / TN);
    const int m0 = blockIdx.y * BM;
    const int n0 = blockIdx.x * BN;

    float acc[TM][TN];
#pragma unroll
    for (int i = 0; i < TM; i++)
#pragma unroll
        for (int j = 0; j < TN; j++) acc[i][j] = 0.f;

    for (int k0 = 0; k0 < K; k0 += BK) {
#pragma unroll
        for (int l = 0; l < ALOAD; l++) {
            int idx = tid + l * THREADS;
            int k = idx % BK, m = idx / BK;
            As[k][m] = A[(size_t)(m0 + m) * lda + k0 + k];
        }
#pragma unroll
        for (int l = 0; l < BLOAD; l++) {
            int idx = tid + l * THREADS;
            int n = idx % BN, k = idx / BN;
            Bs[k][n] = B[(size_t)(k0 + k) * ldb + n0 + n];
        }
        __syncthreads();
#pragma unroll
        for (int kk = 0; kk < BK; kk++) {
            float a[TM], b[TN];
#pragma unroll
            for (int i = 0; i < TM; i++) a[i] = As[kk][ty * TM + i];
#pragma unroll
            for (int j = 0; j < TN; j++) b[j] = Bs[kk][tx * TN + j];
#pragma unroll
            for (int i = 0; i < TM; i++)
#pragma unroll
                for (int j = 0; j < TN; j++) acc[i][j] += a[i] * b[j];
        }
        __syncthreads();
    }
#pragma unroll
    for (int i = 0; i < TM; i++)
#pragma unroll
        for (int j = 0; j < TN; j++) {
            int n = n0 + tx * TN + j;
            float v = acc[i][j] + bias[n];
            size_t o = (size_t)(m0 + ty * TM + i) * ldc + n;
            C[o] = v;
            Cb[o] = __float2bfloat16(v);
        }
}

// ---------------- XWx bf16 MMA ----------------
__global__ void __launch_bounds__(256)
xwx_mma_kernel() {
    __shared__ __align__(16) __nv_bfloat16 As[2][128][40];
    __shared__ __align__(16) __nv_bfloat16 Bs[2][128][40];
    int tid = threadIdx.x;
    int lane = tid & 31, wid = tid >> 5;
    int wm = wid & 1, wn = wid >> 1;
    int m0 = blockIdx.x * 128;
    int n0 = blockIdx.y * 128;

    float acc[4][4][4];
#pragma unroll
    for (int a = 0; a < 4; a++)
#pragma unroll
        for (int b = 0; b < 4; b++)
#pragma unroll
            for (int c = 0; c < 4; c++) acc[a][b][c] = 0.f;

    auto loadA = [&](int s, int k0) {
#pragma unroll
        for (int l = 0; l < 2; l++) {
            int idx = tid + l * 256;
            int row = idx >> 2, ch = idx & 3;
            cp16(&As[s][row][ch * 8], g_xg + (size_t)(m0 + row) * WD + k0 + ch * 8);
        }
    };
    auto loadB = [&](int s, int k0) {
#pragma unroll
        for (int l = 0; l < 2; l++) {
            int idx = tid + l * 256;
            int row = idx >> 2, ch = idx & 3;
            cp16(&Bs[s][row][ch * 8], g_WxiT + (size_t)(n0 + row) * WD + k0 + ch * 8);
        }
    };
    loadA(0, 0); loadB(0, 0); cp_commit();

    constexpr int NIT = WD / 32;  // 8
    for (int it = 0; it < NIT; it++) {
        if (it + 1 < NIT) {
            int s = (it + 1) & 1;
            loadA(s, (it + 1) * 32); loadB(s, (it + 1) * 32);
            cp_commit(); cp_wait<1>();
        } else cp_wait<0>();
        __syncthreads();
        int s = it & 1;
        uint32_t aBase = smem_u32(&As[s][0][0]);
        uint32_t bBase = smem_u32(&Bs[s][0][0]);
#pragma unroll
        for (int ks = 0; ks < 2; ks++) {
            uint32_t a[4][4], b[4][2];
#pragma unroll
            for (int mf = 0; mf < 4; mf++) {
                int row = wm * 64 + mf * 16 + (lane & 15);
                ldsm4(a[mf][0], a[mf][1], a[mf][2], a[mf][3],
                      aBase + row * 80 + (ks * 16 + (lane >> 4) * 8) * 2);
            }
#pragma unroll
            for (int nf = 0; nf < 4; nf++) {
                int row = wn * 32 + nf * 8 + (lane & 7);
                ldsm2(b[nf][0], b[nf][1],
                      bBase + row * 80 + (ks * 16 + ((lane >> 3) & 1) * 8) * 2);
            }
#pragma unroll
            for (int mf = 0; mf < 4; mf++)
#pragma unroll
                for (int nf = 0; nf < 4; nf++)
                    mma16816(acc[mf][nf], a[mf], b[nf]);
        }
        __syncthreads();
    }

#pragma unroll
    for (int mf = 0; mf < 4; mf++) {
        int r = m0 + wm * 64 + mf * 16 + (lane >> 2);
#pragma unroll
        for (int nf = 0; nf < 4; nf++) {
            int c = n0 + wn * 32 + nf * 8 + 2 * (lane & 3);
            float b0 = g_bi[c], b1 = g_bi[c + 1];
            float2 v0 = {acc[mf][nf][0] + b0, acc[mf][nf][1] + b1};
            float2 v1 = {acc[mf][nf][2] + b0, acc[mf][nf][3] + b1};
            *(float2*)&g_XWx[(size_t)r * G4 + c] = v0;
            *(float2*)&g_XWx[(size_t)(r + 8) * G4 + c] = v1;
        }
    }
}

// ---------------- persistent LSTM: all 32 steps, grid barrier ----------------
// 64 blocks (co-resident), Wh slice resident in smem, A 3-stage streamed.
__global__ void __launch_bounds__(256, 1)
lstm_persistent_kernel() {
    extern __shared__ __align__(16) char dynsm[];
    uint32_t bsU = smem_u32(dynsm);               // B: 32 rows x 1040B (odd granule)
    uint32_t asU = bsU + L_AS_O;                  // A: 3 stages x 128 x 80B

    int tid = threadIdx.x;
    int lane = tid & 31, wid = tid >> 5;
    int wm = wid >> 2, wn = wid & 3;              // warp tile 64m x 8n
    int n0 = blockIdx.x * 32;

    // load resident B slice (32 x 512 bf16) once
#pragma unroll
    for (int l = 0; l < 8; l++) {
        int idx = tid + l * 256;                  // 2048 x 16B
        int row = idx >> 6, ch = idx & 63;
        cp16a(bsU + row * 1040 + ch * 16, g_WhiT + (size_t)(n0 + row) * HH + ch * 8);
    }
    cp_commit(); cp_wait<0>();
    __syncthreads();

    int cbase = n0 + wn * 8 + 2 * (lane & 3);
    int j = cbase >> 2;

    for (int t = 0; t < TT; t++) {
        const __nv_bfloat16* Aptr = (t == 0) ? g_h0b : (g_hb + (size_t)(t - 1) * HH);
        const int rowStride = (t == 0) ? HH : (TT * HH);

        auto loadA = [&](int s, int k0) {
#pragma unroll
            for (int l = 0; l < 2; l++) {
                int idx = tid + l * 256;
                int row = idx >> 2, ch = idx & 3;
                cp16a(asU + s * 10240 + row * 80 + ch * 16,
                      Aptr + (size_t)row * rowStride + k0 + ch * 8);
            }
            cp_commit();
        };

        float acc[4][4];
#pragma unroll
        for (int a = 0; a < 4; a++)
#pragma unroll
            for (int c = 0; c < 4; c++) acc[a][c] = 0.f;

        loadA(0, 0);
        loadA(1, 32);

        for (int it = 0; it < 16; it++) {
            if (it < 15) cp_wait<1>(); else cp_wait<0>();
            __syncthreads();
            if (it + 2 < 16) loadA((it + 2) % 3, (it + 2) * 32);
            int s = it % 3;
#pragma unroll
            for (int ks = 0; ks < 2; ks++) {
                uint32_t a[4][4], b[2];
#pragma unroll
                for (int mf = 0; mf < 4; mf++) {
                    int row = wm * 64 + mf * 16 + (lane & 15);
                    ldsm4(a[mf][0], a[mf][1], a[mf][2], a[mf][3],
                          asU + s * 10240 + row * 80 + (ks * 16 + (lane >> 4) * 8) * 2);
                }
                {
                    int row = wn * 8 + (lane & 7);
                    ldsm2(b[0], b[1],
                          bsU + row * 1040 + (it * 32 + ks * 16 + ((lane >> 3) & 1) * 8) * 2);
                }
#pragma unroll
                for (int mf = 0; mf < 4; mf++)
                    mma16816(acc[mf], a[mf], b);
            }
        }

        // fused gate epilogue (identical math to the per-step kernel)
#pragma unroll
        for (int mf = 0; mf < 4; mf++) {
            int r = wm * 64 + mf * 16 + (lane >> 2);
            float2 x0 = *(const float2*)&g_XWx[(size_t)((r << 5) + t) * G4 + cbase];
            float2 x1 = *(const float2*)&g_XWx[(size_t)(((r + 8) << 5) + t) * G4 + cbase];
            float v0 = acc[mf][0] + x0.x, v1 = acc[mf][1] + x0.y;
            float v2 = acc[mf][2] + x1.x, v3 = acc[mf][3] + x1.y;
            float e0 = __shfl_xor_sync(0xffffffffu, v0, 1);
            float e1 = __shfl_xor_sync(0xffffffffu, v1, 1);
            float e2 = __shfl_xor_sync(0xffffffffu, v2, 1);
            float e3 = __shfl_xor_sync(0xffffffffu, v3, 1);
            if (!(lane & 1)) {
                {
                    float i_ = sigmoidf_(v0), f_ = sigmoidf_(v1);
                    float o_ = sigmoidf_(e0), gg = tanhf(e1);
                    float cp = t ? g_c[r * HH + j] : 0.f;
                    float cn = f_ * cp + i_ * gg;
                    float hv = o_ * tanhf(cn);
                    g_c[r * HH + j] = cn;
                    size_t hi = (size_t)((r << 5) + t) * HH + j;
                    g_hb[hi] = __float2bfloat16(hv);
                    g_h8[hi] = q8h(hv);
                }
                {
                    int r8 = r + 8;
                    float i_ = sigmoidf_(v2), f_ = sigmoidf_(v3);
                    float o_ = sigmoidf_(e2), gg = tanhf(e3);
                    float cp = t ? g_c[r8 * HH + j] : 0.f;
                    float cn = f_ * cp + i_ * gg;
                    float hv = o_ * tanhf(cn);
                    g_c[r8 * HH + j] = cn;
                    size_t hi = (size_t)((r8 << 5) + t) * HH + j;
                    g_hb[hi] = __float2bfloat16(hv);
                    g_h8[hi] = q8h(hv);
                }
            }
        }

        // deterministic grid barrier (cumulative counter + phase)
        __syncthreads();
        if (tid == 0) {
            __threadfence();
            int old = atomicAdd(&g_bar_cnt, 1);
            if (old == NBLK * (t + 1) - 1)
                atomicExch(&g_bar_phase, t + 1);
            while (*(volatile int*)&g_bar_phase < t + 1) __nanosleep(64);
            __threadfence();
        }
        __syncthreads();
    }
}

// ---------------- vocab INT8 MMA GEMM (3-stage, one sync/iter) --------------
__global__ void __launch_bounds__(256)
vocab_s8_kernel(const float* __restrict__ bv) {
    extern __shared__ __align__(16) char dynsm[];
    uint32_t aU = smem_u32(dynsm);
    uint32_t bU = aU + V_AS_B;
    float (*sred)[VBM] = (float (*)[VBM])(dynsm + V_SR_O);

    int tid = threadIdx.x;
    int lane = tid & 31, wid = tid >> 5;
    int wm = wid & 1, wn = wid >> 1;
    int m0 = blockIdx.x * VBM;
    int n0 = blockIdx.y * VBN;

    int acc[4][4][4];
#pragma unroll
    for (int a = 0; a < 4; a++)
#pragma unroll
        for (int b = 0; b < 4; b++)
#pragma unroll
            for (int c = 0; c < 4; c++) acc[a][b][c] = 0;

    auto loadAB = [&](int s, int k0) {
#pragma unroll
        for (int l = 0; l < 2; l++) {
            int idx = tid + l * 256;
            int row = idx >> 2, ch = idx & 3;
            cp16a(aU + s * 10240 + row * 80 + ch * 16,
                  g_h8 + (size_t)(m0 + row) * HH + k0 + ch * 16);
            cp16a(bU + s * 10240 + row * 80 + ch * 16,
                  g_w8 + (size_t)(n0 + row) * HH + k0 + ch * 16);
        }
        cp_commit();
    };

    loadAB(0, 0);
    loadAB(1, 64);

    constexpr int NIT = HH / 64;  // 8
    for (int it = 0; it < NIT; it++) {
        if (it < NIT - 1) cp_wait<1>(); else cp_wait<0>();
        __syncthreads();
        if (it + 2 < NIT) loadAB((it + 2) % 3, (it + 2) * 64);
        int s = it % 3;
#pragma unroll
        for (int ks = 0; ks < 2; ks++) {
            uint32_t a[4][4], b[4][2];
#pragma unroll
            for (int mf = 0; mf < 4; mf++) {
                int row = wm * 64 + mf * 16 + (lane & 15);
                ldsm4(a[mf][0], a[mf][1], a[mf][2], a[mf][3],
                      aU + s * 10240 + row * 80 + ks * 32 + (lane >> 4) * 16);
            }
#pragma unroll
            for (int nf = 0; nf < 4; nf++) {
                int row = wn * 32 + nf * 8 + (lane & 7);
                ldsm2(b[nf][0], b[nf][1],
                      bU + s * 10240 + row * 80 + ks * 32 + ((lane >> 3) & 1) * 16);
            }
#pragma unroll
            for (int mf = 0; mf < 4; mf++)
#pragma unroll
                for (int nf = 0; nf < 4; nf++)
                    mma16832s8(acc[mf][nf], a[mf], b[nf]);
        }
    }

    const float INV = 1.f / (HSC * WSC);
    float rowsum[4][2] = {};
#pragma unroll
    for (int nf = 0; nf < 4; nf++) {
        int nb_ = n0 + wn * 32 + nf * 8 + 2 * (lane & 3);
        float b0 = bv[nb_], b1 = bv[nb_ + 1];
#pragma unroll
        for (int mf = 0; mf < 4; mf++) {
            rowsum[mf][0] += __expf(fmaf((float)acc[mf][nf][0], INV, b0))
                           + __expf(fmaf((float)acc[mf][nf][1], INV, b1));
            rowsum[mf][1] += __expf(fmaf((float)acc[mf][nf][2], INV, b0))
                           + __expf(fmaf((float)acc[mf][nf][3], INV, b1));
        }
    }
#pragma unroll
    for (int mf = 0; mf < 4; mf++)
#pragma unroll
        for (int h = 0; h < 2; h++) {
            rowsum[mf][h] += __shfl_xor_sync(0xffffffffu, rowsum[mf][h], 1);
            rowsum[mf][h] += __shfl_xor_sync(0xffffffffu, rowsum[mf][h], 2);
        }
    __syncthreads();
    if ((lane & 3) == 0) {
#pragma unroll
        for (int mf = 0; mf < 4; mf++) {
            int r = wm * 64 + mf * 16 + (lane >> 2);
            sred[wn][r]     = rowsum[mf][0];
            sred[wn][r + 8] = rowsum[mf][1];
        }
    }
    __syncthreads();
    if (tid < VBM) {
        float s = sred[0][tid] + sred[1][tid] + sred[2][tid] + sred[3][tid];
        g_part[(size_t)(m0 + tid) * NTILES_V + blockIdx.y] = s;
    }
}

// ---------------- merged target-score + nll (one warp per token) ------------
__global__ void nll_tsc_kernel(const float* __restrict__ bv) {
    int w = (blockIdx.x * blockDim.x + threadIdx.x) >> 5;
    int lane = threadIdx.x & 31;
    if (w >= M_NT) return;
    int tgt = g_tgt[w];

    // target score (bf16 path)
    const uint4* h4 = (const uint4*)(g_hb + (size_t)w * HH);
    const uint4* w4 = (const uint4*)(g_wt + (size_t)tgt * HH);
    float ts = 0.f;
#pragma unroll
    for (int i = 0; i < 2; i++) {
        uint4 a = h4[lane + i * 32];
        uint4 b = w4[lane + i * 32];
        const uint32_t* ap = &a.x;
        const uint32_t* bp = &b.x;
#pragma unroll
        for (int q = 0; q < 4; q++) {
            float2 fa = __bfloat1622float2(*(const __nv_bfloat162*)&ap[q]);
            float2 fb = __bfloat1622float2(*(const __nv_bfloat162*)&bp[q]);
            ts += fa.x * fb.x + fa.y * fb.y;
        }
    }
    // partial-sum reduction
    const float* p = g_part + (size_t)w * NTILES_V;
    float se = 0.f;
    for (int i = lane; i < NTILES_V; i += 32) se += p[i];
#pragma unroll
    for (int off = 16; off; off >>= 1) {
        ts += __shfl_down_sync(0xffffffffu, ts, off);
        se += __shfl_down_sync(0xffffffffu, se, off);
    }
    if (lane == 0)
        g_nll[w] = (tgt != 0) ? (logf(se) - (ts + bv[tgt])) : 0.f;
}

__global__ void loss_kernel(float* __restrict__ out) {
    __shared__ float sm[256];
    float s = 0.f;
    for (int i = threadIdx.x; i < M_NT; i += 256) s += g_nll[i];
    sm[threadIdx.x] = s;
    __syncthreads();
    for (int off = 128; off; off >>= 1) {
        if (threadIdx.x < off) sm[threadIdx.x] += sm[threadIdx.x + off];
        __syncthreads();
    }
    if (threadIdx.x == 0) out[0] = sm[0] / (float)NB;
}

// ---------------- launch ----------------
extern "C" void kernel_launch(void* const* d_in, const int* in_sizes, int n_in,
                              void* d_out, int out_size) {
    const float* features = (const float*)d_in[0];
    const void*  captions =               d_in[1];
    const float* W_proj   = (const float*)d_in[2];
    const float* b_proj   = (const float*)d_in[3];
    const float* W_embed  = (const float*)d_in[4];
    const float* Wx       = (const float*)d_in[5];
    const float* Wh       = (const float*)d_in[6];
    const float* bb       = (const float*)d_in[7];
    const float* W_vocab  = (const float*)d_in[8];
    const float* b_vocab  = (const float*)d_in[9];
    float* out = (float*)d_out;

    float *p_h0, *p_bi;
    __nv_bfloat16 *p_WxiT, *p_WhiT, *p_h0b;
    cudaGetSymbolAddress((void**)&p_h0,   g_h0);
    cudaGetSymbolAddress((void**)&p_bi,   g_bi);
    cudaGetSymbolAddress((void**)&p_WxiT, g_WxiT);
    cudaGetSymbolAddress((void**)&p_WhiT, g_WhiT);
    cudaGetSymbolAddress((void**)&p_h0b,  g_h0b);

    cudaFuncSetAttribute(lstm_persistent_kernel,
                         cudaFuncAttributeMaxDynamicSharedMemorySize, L_SMEM);
    cudaFuncSetAttribute(vocab_s8_kernel,
                         cudaFuncAttributeMaxDynamicSharedMemorySize, V_SMEM);

    // 0. indices + barrier reset + weight conversions
    detect_kernel<<<1, 256>>>((const unsigned int*)captions);
    build_idx_kernel<<<(M_NT + 255) / 256, 256>>>(captions);
    reorder_bias_kernel<<<(G4 + 255) / 256, 256>>>(bb, p_bi);
    transT_gate_kernel<<<dim3(G4 / 32, WD / 32), dim3(32, 8)>>>(Wx, p_WxiT, WD);
    transT_gate_kernel<<<dim3(G4 / 32, HH / 32), dim3(32, 8)>>>(Wh, p_WhiT, HH);
    convW_kernel<<<dim3(VV / 32, HH / 32), dim3(32, 8)>>>(W_vocab);
    gatherconv_kernel<<<(M_NT * WD + 255) / 256, 256>>>(W_embed);

    // 1. h0 (fp32 + bf16 in one pass)
    sgemm_k<32, 64, 16, 2, 4><<<dim3(HH / 64, NB / 32), 256>>>(
        features, DF, W_proj, HH, p_h0, HH, p_h0b, b_proj, DF);

    // 2. XWx
    xwx_mma_kernel<<<dim3(M_NT / 128, G4 / 128), 256>>>();

    // 3. persistent LSTM (all 32 steps, 64 co-resident blocks)
    lstm_persistent_kernel<<<NBLK, 256, L_SMEM>>>();

    // 4. vocab INT8 MMA GEMM + fused sum-exp (3-stage pipeline)
    vocab_s8_kernel<<<dim3(M_NT / VBM, NTILES_V), 256, V_SMEM>>>(b_vocab);

    // 5. merged tscore+nll, final loss
    nll_tsc_kernel<<<M_NT / 4, 128>>>(b_vocab);
    loss_kernel<<<1, 256>>>(out);
}

// round 10
// speedup vs baseline: 1.4875x; 1.0603x over previous
#include <cuda_runtime.h>
#include <cuda_bf16.h>
#include <math.h>
#include <stdint.h>

// Problem constants
#define NB   128
#define TT   32
#define NTOK (128*33)
#define DF   1280
#define WD   256
#define HH   512
#define VV   32000
#define M_NT (NB*TT)      // 4096
#define G4   2048
#define VBM  128
#define VBN  128
#define NTILES_V (VV/VBN) // 250
#define HSC  127.0f
#define WSC  448.0f
#define NBLK 64           // LSTM worker blocks

// ---- vocab smem layout (3-stage): As 3*128*80 | Bs 3*128*80 | sred
#define V_AS_B  (3 * VBM * 80)
#define V_BS_B  (3 * VBN * 80)
#define V_SR_O  (V_AS_B + V_BS_B)
// ---- LSTM smem layout: Bs 32*1040 | As 3*128*80
#define L_BS_B  (32 * 1040)
#define L_AS_O  L_BS_B
#define M_SMEM  (L_BS_B + 3 * 128 * 80)        // 64000 (covers vocab's 63488 too)

// ---------------- device scratch (ALL m-indexed arrays are t-major: m'=t*128+n)
__device__ __nv_bfloat16 g_hb[(size_t)M_NT * HH];
__device__ signed char   g_h8[(size_t)M_NT * HH];
__device__ __nv_bfloat16 g_wt[(size_t)VV * HH];
__device__ signed char   g_w8[(size_t)VV * HH];
__device__ __nv_bfloat16 g_WxiT[(size_t)G4 * WD];
__device__ __nv_bfloat16 g_WhiT[(size_t)G4 * HH];
__device__ __nv_bfloat16 g_xg[(size_t)M_NT * WD];
__device__ float g_XWx[(size_t)M_NT * G4];
__device__ float g_h0[NB * HH];
__device__ __nv_bfloat16 g_h0b[NB * HH];
__device__ float g_c[NB * HH];
__device__ float g_bi[G4];
__device__ float g_part[(size_t)M_NT * NTILES_V];
__device__ float g_nll[M_NT];
__device__ int   g_rows[M_NT];
__device__ int   g_tgt[M_NT];
__device__ int   g_is64;
__device__ int   g_bar_cnt;
__device__ int   g_bar_phase;
__device__ int   g_w8done[NTILES_V];

// ---------------- small helpers ----------------
__device__ __forceinline__ float sigmoidf_(float x) { return 1.f / (1.f + __expf(-x)); }
__device__ __forceinline__ uint32_t smem_u32(const void* p) {
    return (uint32_t)__cvta_generic_to_shared(p);
}
__device__ __forceinline__ void cp16(void* dst, const void* src) {
    asm volatile("cp.async.cg.shared.global [%0], [%1], 16;"
                 :: "r"(smem_u32(dst)), "l"(src));
}
__device__ __forceinline__ void cp16a(uint32_t dst, const void* src) {
    asm volatile("cp.async.cg.shared.global [%0], [%1], 16;"
                 :: "r"(dst), "l"(src));
}
__device__ __forceinline__ void cp_commit() { asm volatile("cp.async.commit_group;"); }
template<int N> __device__ __forceinline__ void cp_wait() {
    asm volatile("cp.async.wait_group %0;" :: "n"(N));
}
__device__ __forceinline__ void ldsm4(uint32_t& r0, uint32_t& r1, uint32_t& r2, uint32_t& r3, uint32_t addr) {
    asm volatile("ldmatrix.sync.aligned.m8n8.x4.shared.b16 {%0,%1,%2,%3}, [%4];"
                 : "=r"(r0), "=r"(r1), "=r"(r2), "=r"(r3) : "r"(addr));
}
__device__ __forceinline__ void ldsm2(uint32_t& r0, uint32_t& r1, uint32_t addr) {
    asm volatile("ldmatrix.sync.aligned.m8n8.x2.shared.b16 {%0,%1}, [%2];"
                 : "=r"(r0), "=r"(r1) : "r"(addr));
}
__device__ __forceinline__ void mma16816(float* c, const uint32_t* a, const uint32_t* b) {
    asm volatile("mma.sync.aligned.m16n8k16.row.col.f32.bf16.bf16.f32 "
                 "{%0,%1,%2,%3}, {%4,%5,%6,%7}, {%8,%9}, {%0,%1,%2,%3};"
                 : "+f"(c[0]), "+f"(c[1]), "+f"(c[2]), "+f"(c[3])
                 : "r"(a[0]), "r"(a[1]), "r"(a[2]), "r"(a[3]), "r"(b[0]), "r"(b[1]));
}
__device__ __forceinline__ void mma16832s8(int* c, const uint32_t* a, const uint32_t* b) {
    asm volatile("mma.sync.aligned.m16n8k32.row.col.s32.s8.s8.s32 "
                 "{%0,%1,%2,%3}, {%4,%5,%6,%7}, {%8,%9}, {%0,%1,%2,%3};"
                 : "+r"(c[0]), "+r"(c[1]), "+r"(c[2]), "+r"(c[3])
                 : "r"(a[0]), "r"(a[1]), "r"(a[2]), "r"(a[3]), "r"(b[0]), "r"(b[1]));
}
__device__ __forceinline__ signed char q8h(float x) {
    return (signed char)__float2int_rn(x * HSC);
}
__device__ __forceinline__ signed char q8w(float x) {
    int v = __float2int_rn(x * WSC);
    v = v > 127 ? 127 : (v < -127 ? -127 : v);
    return (signed char)v;
}

// ---------------- caption dtype detection + index build (t-major) ----------
__global__ void detect_kernel(const unsigned int* __restrict__ w) {
    __shared__ int found;
    if (threadIdx.x == 0) found = 0;
    __syncthreads();
    for (int i = threadIdx.x; i < NTOK / 2; i += blockDim.x)
        if (w[2 * i + 1] != 0u) found = 1;
    __syncthreads();
    if (threadIdx.x == 0) g_is64 = (found == 0) ? 1 : 0;
}

__global__ void build_idx_kernel(const void* __restrict__ caps) {
    int m = blockIdx.x * blockDim.x + threadIdx.x;
    if (m < NTILES_V) g_w8done[m] = 0;
    if (m == M_NT - 1) { g_bar_cnt = 0; g_bar_phase = 0; }
    if (m >= M_NT) return;
    int t = m >> 7, n = m & 127;            // t-major
    int ci, co;
    if (g_is64) {
        const long long* c = (const long long*)caps;
        ci = (int)c[n * 33 + t];  co = (int)c[n * 33 + t + 1];
    } else {
        const int* c = (const int*)caps;
        ci = c[n * 33 + t];       co = c[n * 33 + t + 1];
    }
    g_rows[m] = ci;  g_tgt[m] = co;
}

// ---------------- bias gate-interleave ----------------
__global__ void reorder_bias_kernel(const float* __restrict__ in, float* __restrict__ out) {
    int np = blockIdx.x * blockDim.x + threadIdx.x;
    if (np >= G4) return;
    int j = np >> 2, g = np & 3;
    out[np] = in[g * HH + j];
}

// ---- transpose + gate-interleave + bf16 ----
__global__ void transT_gate_kernel(const float* __restrict__ in, __nv_bfloat16* __restrict__ out, int K) {
    __shared__ float tile[32][33];
    int np0 = blockIdx.x * 32, k0 = blockIdx.y * 32;
    int tx = threadIdx.x, ty = threadIdx.y;  // 32 x 8
#pragma unroll
    for (int r = 0; r < 4; r++)
        tile[ty + r * 8][tx] = in[(size_t)(k0 + ty + r * 8) * G4 + np0 + tx];
    __syncthreads();
#pragma unroll
    for (int r = 0; r < 4; r++) {
        int npl = ty + r * 8;
        int np = np0 + npl;
        int g = np >> 9, j = np & 511;
        int n = (j << 2) + g;
        out[(size_t)n * K + k0 + tx] = __float2bfloat16(tile[tx][npl]);
    }
}

__global__ void gatherconv_kernel(const float* __restrict__ We) {
    int idx = blockIdx.x * blockDim.x + threadIdx.x;
    if (idx >= M_NT * WD) return;
    int m = idx >> 8, k = idx & (WD - 1);
    g_xg[idx] = __float2bfloat16(We[(size_t)g_rows[m] * WD + k]);
}

// ---------------- fp32 SGEMM (h0; emits bf16 copy) ----------------
template<int BM, int BN, int BK, int TM, int TN>
__global__ void __launch_bounds__(256)
sgemm_k(const float* __restrict__ A, int lda,
        const float* __restrict__ B, int ldb,
        float* __restrict__ C, int ldc,
        __nv_bfloat16* __restrict__ Cb,
        const float* __restrict__ bias, int K)
{
    constexpr int THREADS = (BM / TM) * (BN / TN);
    constexpr int ALOAD = BM * BK / THREADS;
    constexpr int BLOAD = BK * BN / THREADS;
    __shared__ float As[BK][BM + 1];
    __shared__ float Bs[BK][BN];
    const int tid = threadIdx.x;
    const int tx = tid % (BN / TN);
    const int ty = tid / (BN / TN);
    const int m0 = blockIdx.y * BM;
    const int n0 = blockIdx.x * BN;

    float acc[TM][TN];
#pragma unroll
    for (int i = 0; i < TM; i++)
#pragma unroll
        for (int j = 0; j < TN; j++) acc[i][j] = 0.f;

    for (int k0 = 0; k0 < K; k0 += BK) {
#pragma unroll
        for (int l = 0; l < ALOAD; l++) {
            int idx = tid + l * THREADS;
            int k = idx % BK, m = idx / BK;
            As[k][m] = A[(size_t)(m0 + m) * lda + k0 + k];
        }
#pragma unroll
        for (int l = 0; l < BLOAD; l++) {
            int idx = tid + l * THREADS;
            int n = idx % BN, k = idx / BN;
            Bs[k][n] = B[(size_t)(k0 + k) * ldb + n0 + n];
        }
        __syncthreads();
#pragma unroll
        for (int kk = 0; kk < BK; kk++) {
            float a[TM], b[TN];
#pragma unroll
            for (int i = 0; i < TM; i++) a[i] = As[kk][ty * TM + i];
#pragma unroll
            for (int j = 0; j < TN; j++) b[j] = Bs[kk][tx * TN + j];
#pragma unroll
            for (int i = 0; i < TM; i++)
#pragma unroll
                for (int j = 0; j < TN; j++) acc[i][j] += a[i] * b[j];
        }
        __syncthreads();
    }
#pragma unroll
    for (int i = 0; i < TM; i++)
#pragma unroll
        for (int j = 0; j < TN; j++) {
            int n = n0 + tx * TN + j;
            float v = acc[i][j] + bias[n];
            size_t o = (size_t)(m0 + ty * TM + i) * ldc + n;
            C[o] = v;
            Cb[o] = __float2bfloat16(v);
        }
}

// ---------------- XWx bf16 MMA (rows are t-major m') ----------------
__global__ void __launch_bounds__(256)
xwx_mma_kernel() {
    __shared__ __align__(16) __nv_bfloat16 As[2][128][40];
    __shared__ __align__(16) __nv_bfloat16 Bs[2][128][40];
    int tid = threadIdx.x;
    int lane = tid & 31, wid = tid >> 5;
    int wm = wid & 1, wn = wid >> 1;
    int m0 = blockIdx.x * 128;
    int n0 = blockIdx.y * 128;

    float acc[4][4][4];
#pragma unroll
    for (int a = 0; a < 4; a++)
#pragma unroll
        for (int b = 0; b < 4; b++)
#pragma unroll
            for (int c = 0; c < 4; c++) acc[a][b][c] = 0.f;

    auto loadA = [&](int s, int k0) {
#pragma unroll
        for (int l = 0; l < 2; l++) {
            int idx = tid + l * 256;
            int row = idx >> 2, ch = idx & 3;
            cp16(&As[s][row][ch * 8], g_xg + (size_t)(m0 + row) * WD + k0 + ch * 8);
        }
    };
    auto loadB = [&](int s, int k0) {
#pragma unroll
        for (int l = 0; l < 2; l++) {
            int idx = tid + l * 256;
            int row = idx >> 2, ch = idx & 3;
            cp16(&Bs[s][row][ch * 8], g_WxiT + (size_t)(n0 + row) * WD + k0 + ch * 8);
        }
    };
    loadA(0, 0); loadB(0, 0); cp_commit();

    constexpr int NIT = WD / 32;  // 8
    for (int it = 0; it < NIT; it++) {
        if (it + 1 < NIT) {
            int s = (it + 1) & 1;
            loadA(s, (it + 1) * 32); loadB(s, (it + 1) * 32);
            cp_commit(); cp_wait<1>();
        } else cp_wait<0>();
        __syncthreads();
        int s = it & 1;
        uint32_t aBase = smem_u32(&As[s][0][0]);
        uint32_t bBase = smem_u32(&Bs[s][0][0]);
#pragma unroll
        for (int ks = 0; ks < 2; ks++) {
            uint32_t a[4][4], b[4][2];
#pragma unroll
            for (int mf = 0; mf < 4; mf++) {
                int row = wm * 64 + mf * 16 + (lane & 15);
                ldsm4(a[mf][0], a[mf][1], a[mf][2], a[mf][3],
                      aBase + row * 80 + (ks * 16 + (lane >> 4) * 8) * 2);
            }
#pragma unroll
            for (int nf = 0; nf < 4; nf++) {
                int row = wn * 32 + nf * 8 + (lane & 7);
                ldsm2(b[nf][0], b[nf][1],
                      bBase + row * 80 + (ks * 16 + ((lane >> 3) & 1) * 8) * 2);
            }
#pragma unroll
            for (int mf = 0; mf < 4; mf++)
#pragma unroll
                for (int nf = 0; nf < 4; nf++)
                    mma16816(acc[mf][nf], a[mf], b[nf]);
        }
        __syncthreads();
    }

#pragma unroll
    for (int mf = 0; mf < 4; mf++) {
        int r = m0 + wm * 64 + mf * 16 + (lane >> 2);
#pragma unroll
        for (int nf = 0; nf < 4; nf++) {
            int c = n0 + wn * 32 + nf * 8 + 2 * (lane & 3);
            float b0 = g_bi[c], b1 = g_bi[c + 1];
            float2 v0 = {acc[mf][nf][0] + b0, acc[mf][nf][1] + b1};
            float2 v1 = {acc[mf][nf][2] + b0, acc[mf][nf][3] + b1};
            *(float2*)&g_XWx[(size_t)r * G4 + c] = v0;
            *(float2*)&g_XWx[(size_t)(r + 8) * G4 + c] = v1;
        }
    }
}

// ============================================================================
// MEGA kernel: [0,64) LSTM | [64,314) convW | [314,8314) vocab consumers
// ============================================================================
__global__ void __launch_bounds__(256)
mega_kernel(const float* __restrict__ Wv, const float* __restrict__ bv) {
    extern __shared__ __align__(16) char dynsm[];
    int role = blockIdx.x;
    int tid = threadIdx.x;
    int lane = tid & 31, wid = tid >> 5;

    if (role < NBLK) {
        // ---------------- LSTM worker ----------------
        uint32_t bsU = smem_u32(dynsm);
        uint32_t asU = bsU + L_AS_O;
        int wm = wid >> 2, wn = wid & 3;
        int n0 = role * 32;

#pragma unroll
        for (int l = 0; l < 8; l++) {
            int idx = tid + l * 256;
            int row = idx >> 6, ch = idx & 63;
            cp16a(bsU + row * 1040 + ch * 16, g_WhiT + (size_t)(n0 + row) * HH + ch * 8);
        }
        cp_commit(); cp_wait<0>();
        __syncthreads();

        int cbase = n0 + wn * 8 + 2 * (lane & 3);
        int j = cbase >> 2;

        for (int t = 0; t < TT; t++) {
            const __nv_bfloat16* Aptr = (t == 0) ? g_h0b : (g_hb + (size_t)(t - 1) * 128 * HH);

            auto loadA = [&](int s, int k0) {
#pragma unroll
                for (int l = 0; l < 2; l++) {
                    int idx = tid + l * 256;
                    int row = idx >> 2, ch = idx & 3;
                    cp16a(asU + s * 10240 + row * 80 + ch * 16,
                          Aptr + (size_t)row * HH + k0 + ch * 8);
                }
                cp_commit();
            };

            float acc[4][4];
#pragma unroll
            for (int a = 0; a < 4; a++)
#pragma unroll
                for (int c = 0; c < 4; c++) acc[a][c] = 0.f;

            loadA(0, 0);
            loadA(1, 32);

            for (int it = 0; it < 16; it++) {
                if (it < 15) cp_wait<1>(); else cp_wait<0>();
                __syncthreads();
                if (it + 2 < 16) loadA((it + 2) % 3, (it + 2) * 32);
                int s = it % 3;
#pragma unroll
                for (int ks = 0; ks < 2; ks++) {
                    uint32_t a[4][4], b[2];
#pragma unroll
                    for (int mf = 0; mf < 4; mf++) {
                        int row = wm * 64 + mf * 16 + (lane & 15);
                        ldsm4(a[mf][0], a[mf][1], a[mf][2], a[mf][3],
                              asU + s * 10240 + row * 80 + (ks * 16 + (lane >> 4) * 8) * 2);
                    }
                    {
                        int row = wn * 8 + (lane & 7);
                        ldsm2(b[0], b[1],
                              bsU + row * 1040 + (it * 32 + ks * 16 + ((lane >> 3) & 1) * 8) * 2);
                    }
#pragma unroll
                    for (int mf = 0; mf < 4; mf++)
                        mma16816(acc[mf], a[mf], b);
                }
            }

#pragma unroll
            for (int mf = 0; mf < 4; mf++) {
                int r = wm * 64 + mf * 16 + (lane >> 2);
                float2 x0 = *(const float2*)&g_XWx[(size_t)(t * 128 + r) * G4 + cbase];
                float2 x1 = *(const float2*)&g_XWx[(size_t)(t * 128 + r + 8) * G4 + cbase];
                float v0 = acc[mf][0] + x0.x, v1 = acc[mf][1] + x0.y;
                float v2 = acc[mf][2] + x1.x, v3 = acc[mf][3] + x1.y;
                float e0 = __shfl_xor_sync(0xffffffffu, v0, 1);
                float e1 = __shfl_xor_sync(0xffffffffu, v1, 1);
                float e2 = __shfl_xor_sync(0xffffffffu, v2, 1);
                float e3 = __shfl_xor_sync(0xffffffffu, v3, 1);
                if (!(lane & 1)) {
                    {
                        float i_ = sigmoidf_(v0), f_ = sigmoidf_(v1);
                        float o_ = sigmoidf_(e0), gg = tanhf(e1);
                        float cp = t ? g_c[r * HH + j] : 0.f;
                        float cn = f_ * cp + i_ * gg;
                        float hv = o_ * tanhf(cn);
                        g_c[r * HH + j] = cn;
                        size_t hi = (size_t)(t * 128 + r) * HH + j;
                        g_hb[hi] = __float2bfloat16(hv);
                        g_h8[hi] = q8h(hv);
                    }
                    {
                        int r8 = r + 8;
                        float i_ = sigmoidf_(v2), f_ = sigmoidf_(v3);
                        float o_ = sigmoidf_(e2), gg = tanhf(e3);
                        float cp = t ? g_c[r8 * HH + j] : 0.f;
                        float cn = f_ * cp + i_ * gg;
                        float hv = o_ * tanhf(cn);
                        g_c[r8 * HH + j] = cn;
                        size_t hi = (size_t)(t * 128 + r8) * HH + j;
                        g_hb[hi] = __float2bfloat16(hv);
                        g_h8[hi] = q8h(hv);
                    }
                }
            }

            // grid barrier among the 64 LSTM blocks; also publishes progress
            __syncthreads();
            if (tid == 0) {
                __threadfence();
                int old = atomicAdd(&g_bar_cnt, 1);
                if (old == NBLK * (t + 1) - 1)
                    atomicExch(&g_bar_phase, t + 1);
                while (*(volatile int*)&g_bar_phase < t + 1) __nanosleep(64);
                __threadfence();
            }
            __syncthreads();
        }
    } else if (role < NBLK + NTILES_V) {
        // ---------------- convW worker: n-range [b*128, b*128+128) ----------
        int b = role - NBLK;
        float (*tile)[33] = (float (*)[33])dynsm;
        int tx = tid & 31, ty = tid >> 5;        // 32 x 8
        for (int kt = 0; kt < 16; kt++) {
            int k0 = kt * 32;
#pragma unroll
            for (int ns = 0; ns < 4; ns++) {
                int n0b = b * 128 + ns * 32;
                __syncthreads();
#pragma unroll
                for (int r = 0; r < 4; r++)
                    tile[ty + r * 8][tx] = Wv[(size_t)(k0 + ty + r * 8) * VV + n0b + tx];
                __syncthreads();
#pragma unroll
                for (int r = 0; r < 4; r++) {
                    int n = ty + r * 8;
                    float w = tile[tx][n];
                    g_wt[(size_t)(n0b + n) * HH + k0 + tx] = __float2bfloat16(w);
                    g_w8[(size_t)(n0b + n) * HH + k0 + tx] = q8w(w);
                }
            }
        }
        __threadfence();
        __syncthreads();
        if (tid == 0) atomicExch(&g_w8done[b], 1);
    } else {
        // ---------------- vocab consumer (t, ntile) ----------------
        int v = role - NBLK - NTILES_V;
        int t = v / NTILES_V, ntile = v % NTILES_V;
        int m0 = t * 128, n0 = ntile * VBN;

        if (tid == 0) {
            while (*(volatile int*)&g_bar_phase < t + 1 ||
                   *(volatile int*)&g_w8done[ntile] == 0)
                __nanosleep(128);
            __threadfence();
        }
        __syncthreads();

        uint32_t aU = smem_u32(dynsm);
        uint32_t bU = aU + V_AS_B;
        float (*sred)[VBM] = (float (*)[VBM])(dynsm + V_SR_O);
        int wm = wid & 1, wn = wid >> 1;

        int acc[4][4][4];
#pragma unroll
        for (int a = 0; a < 4; a++)
#pragma unroll
            for (int b2 = 0; b2 < 4; b2++)
#pragma unroll
                for (int c = 0; c < 4; c++) acc[a][b2][c] = 0;

        auto loadAB = [&](int s, int k0) {
#pragma unroll
            for (int l = 0; l < 2; l++) {
                int idx = tid + l * 256;
                int row = idx >> 2, ch = idx & 3;
                cp16a(aU + s * 10240 + row * 80 + ch * 16,
                      g_h8 + (size_t)(m0 + row) * HH + k0 + ch * 16);
                cp16a(bU + s * 10240 + row * 80 + ch * 16,
                      g_w8 + (size_t)(n0 + row) * HH + k0 + ch * 16);
            }
            cp_commit();
        };

        loadAB(0, 0);
        loadAB(1, 64);

        constexpr int NIT = HH / 64;  // 8
        for (int it = 0; it < NIT; it++) {
            if (it < NIT - 1) cp_wait<1>(); else cp_wait<0>();
            __syncthreads();
            if (it + 2 < NIT) loadAB((it + 2) % 3, (it + 2) * 64);
            int s = it % 3;
#pragma unroll
            for (int ks = 0; ks < 2; ks++) {
                uint32_t a[4][4], b[4][2];
#pragma unroll
                for (int mf = 0; mf < 4; mf++) {
                    int row = wm * 64 + mf * 16 + (lane & 15);
                    ldsm4(a[mf][0], a[mf][1], a[mf][2], a[mf][3],
                          aU + s * 10240 + row * 80 + ks * 32 + (lane >> 4) * 16);
                }
#pragma unroll
                for (int nf = 0; nf < 4; nf++) {
                    int row = wn * 32 + nf * 8 + (lane & 7);
                    ldsm2(b[nf][0], b[nf][1],
                          bU + s * 10240 + row * 80 + ks * 32 + ((lane >> 3) & 1) * 16);
                }
#pragma unroll
                for (int mf = 0; mf < 4; mf++)
#pragma unroll
                    for (int nf = 0; nf < 4; nf++)
                        mma16832s8(acc[mf][nf], a[mf], b[nf]);
            }
        }

        const float INV = 1.f / (HSC * WSC);
        float rowsum[4][2] = {};
#pragma unroll
        for (int nf = 0; nf < 4; nf++) {
            int nb_ = n0 + wn * 32 + nf * 8 + 2 * (lane & 3);
            float b0 = bv[nb_], b1 = bv[nb_ + 1];
#pragma unroll
            for (int mf = 0; mf < 4; mf++) {
                rowsum[mf][0] += __expf(fmaf((float)acc[mf][nf][0], INV, b0))
                               + __expf(fmaf((float)acc[mf][nf][1], INV, b1));
                rowsum[mf][1] += __expf(fmaf((float)acc[mf][nf][2], INV, b0))
                               + __expf(fmaf((float)acc[mf][nf][3], INV, b1));
            }
        }
#pragma unroll
        for (int mf = 0; mf < 4; mf++)
#pragma unroll
            for (int h = 0; h < 2; h++) {
                rowsum[mf][h] += __shfl_xor_sync(0xffffffffu, rowsum[mf][h], 1);
                rowsum[mf][h] += __shfl_xor_sync(0xffffffffu, rowsum[mf][h], 2);
            }
        __syncthreads();
        if ((lane & 3) == 0) {
#pragma unroll
            for (int mf = 0; mf < 4; mf++) {
                int r = wm * 64 + mf * 16 + (lane >> 2);
                sred[wn][r]     = rowsum[mf][0];
                sred[wn][r + 8] = rowsum[mf][1];
            }
        }
        __syncthreads();
        if (tid < VBM) {
            float s = sred[0][tid] + sred[1][tid] + sred[2][tid] + sred[3][tid];
            g_part[(size_t)(m0 + tid) * NTILES_V + ntile] = s;
        }
    }
}

// ---------------- merged target-score + nll (one warp per token) ------------
__global__ void nll_tsc_kernel(const float* __restrict__ bv) {
    int w = (blockIdx.x * blockDim.x + threadIdx.x) >> 5;
    int lane = threadIdx.x & 31;
    if (w >= M_NT) return;
    int tgt = g_tgt[w];

    const uint4* h4 = (const uint4*)(g_hb + (size_t)w * HH);
    const uint4* w4 = (const uint4*)(g_wt + (size_t)tgt * HH);
    float ts = 0.f;
#pragma unroll
    for (int i = 0; i < 2; i++) {
        uint4 a = h4[lane + i * 32];
        uint4 b = w4[lane + i * 32];
        const uint32_t* ap = &a.x;
        const uint32_t* bp = &b.x;
#pragma unroll
        for (int q = 0; q < 4; q++) {
            float2 fa = __bfloat1622float2(*(const __nv_bfloat162*)&ap[q]);
            float2 fb = __bfloat1622float2(*(const __nv_bfloat162*)&bp[q]);
            ts += fa.x * fb.x + fa.y * fb.y;
        }
    }
    const float* p = g_part + (size_t)w * NTILES_V;
    float se = 0.f;
    for (int i = lane; i < NTILES_V; i += 32) se += p[i];
#pragma unroll
    for (int off = 16; off; off >>= 1) {
        ts += __shfl_down_sync(0xffffffffu, ts, off);
        se += __shfl_down_sync(0xffffffffu, se, off);
    }
    if (lane == 0)
        g_nll[w] = (tgt != 0) ? (logf(se) - (ts + bv[tgt])) : 0.f;
}

__global__ void loss_kernel(float* __restrict__ out) {
    __shared__ float sm[256];
    float s = 0.f;
    for (int i = threadIdx.x; i < M_NT; i += 256) s += g_nll[i];
    sm[threadIdx.x] = s;
    __syncthreads();
    for (int off = 128; off; off >>= 1) {
        if (threadIdx.x < off) sm[threadIdx.x] += sm[threadIdx.x + off];
        __syncthreads();
    }
    if (threadIdx.x == 0) out[0] = sm[0] / (float)NB;
}

// ---------------- launch ----------------
extern "C" void kernel_launch(void* const* d_in, const int* in_sizes, int n_in,
                              void* d_out, int out_size) {
    const float* features = (const float*)d_in[0];
    const void*  captions =               d_in[1];
    const float* W_proj   = (const float*)d_in[2];
    const float* b_proj   = (const float*)d_in[3];
    const float* W_embed  = (const float*)d_in[4];
    const float* Wx       = (const float*)d_in[5];
    const float* Wh       = (const float*)d_in[6];
    const float* bb       = (const float*)d_in[7];
    const float* W_vocab  = (const float*)d_in[8];
    const float* b_vocab  = (const float*)d_in[9];
    float* out = (float*)d_out;

    float *p_h0, *p_bi;
    __nv_bfloat16 *p_WxiT, *p_WhiT, *p_h0b;
    cudaGetSymbolAddress((void**)&p_h0,   g_h0);
    cudaGetSymbolAddress((void**)&p_bi,   g_bi);
    cudaGetSymbolAddress((void**)&p_WxiT, g_WxiT);
    cudaGetSymbolAddress((void**)&p_WhiT, g_WhiT);
    cudaGetSymbolAddress((void**)&p_h0b,  g_h0b);

    cudaFuncSetAttribute(mega_kernel,
                         cudaFuncAttributeMaxDynamicSharedMemorySize, M_SMEM);

    // 0. indices + flag resets + prep
    detect_kernel<<<1, 256>>>((const unsigned int*)captions);
    build_idx_kernel<<<(M_NT + 255) / 256, 256>>>(captions);
    reorder_bias_kernel<<<(G4 + 255) / 256, 256>>>(bb, p_bi);
    transT_gate_kernel<<<dim3(G4 / 32, WD / 32), dim3(32, 8)>>>(Wx, p_WxiT, WD);
    transT_gate_kernel<<<dim3(G4 / 32, HH / 32), dim3(32, 8)>>>(Wh, p_WhiT, HH);
    gatherconv_kernel<<<(M_NT * WD + 255) / 256, 256>>>(W_embed);

    // 1. h0 (fp32 + bf16 in one pass)
    sgemm_k<32, 64, 16, 2, 4><<<dim3(HH / 64, NB / 32), 256>>>(
        features, DF, W_proj, HH, p_h0, HH, p_h0b, b_proj, DF);

    // 2. XWx (t-major rows)
    xwx_mma_kernel<<<dim3(M_NT / 128, G4 / 128), 256>>>();

    // 3. MEGA: LSTM + convW + vocab, overlapped via progress flags
    mega_kernel<<<NBLK + NTILES_V + TT * NTILES_V, 256, M_SMEM>>>(W_vocab, b_vocab);

    // 4. merged tscore+nll, final loss
    nll_tsc_kernel<<<M_NT / 4, 128>>>(b_vocab);
    loss_kernel<<<1, 256>>>(out);
}

// round 11
// speedup vs baseline: 1.9222x; 1.2923x over previous
#include <cuda_runtime.h>
#include <cuda_bf16.h>
#include <math.h>
#include <stdint.h>

// Problem constants
#define NB   128
#define TT   32
#define NTOK (128*33)
#define DF   1280
#define WD   256
#define HH   512
#define VV   32000
#define M_NT (NB*TT)      // 4096
#define G4   2048
#define VBM  128
#define VBN  128
#define NTILES_V (VV/VBN) // 250
#define HSC  127.0f
#define WSC  448.0f
#define NBLK 64           // LSTM worker blocks

// mega role ranges
#define R_H0    0
#define R_LSTM  32
#define R_CONVW (R_LSTM + NBLK)            // 96
#define R_XWX   (R_CONVW + NTILES_V)       // 346
#define R_VOC   (R_XWX + 512)              // 858
#define R_END   (R_VOC + TT * NTILES_V)    // 8858

// ---- vocab smem layout (3-stage): As 3*128*80 | Bs 3*128*80 | sred
#define V_AS_B  (3 * VBM * 80)
#define V_BS_B  (3 * VBN * 80)
#define V_SR_O  (V_AS_B + V_BS_B)
// ---- LSTM smem layout: Bs 32*1040 | As 3*128*80
#define L_BS_B  (32 * 1040)
#define L_AS_O  L_BS_B
#define M_SMEM  (L_BS_B + 3 * 128 * 80)    // 64000 (max over all roles)

// ---------------- device scratch (m-indexed arrays are t-major: m'=t*128+n)
__device__ __nv_bfloat16 g_hb[(size_t)M_NT * HH];
__device__ signed char   g_h8[(size_t)M_NT * HH];
__device__ __nv_bfloat16 g_wt[(size_t)VV * HH];
__device__ signed char   g_w8[(size_t)VV * HH];
__device__ __nv_bfloat16 g_WxiT[(size_t)G4 * WD];
__device__ __nv_bfloat16 g_WhiT[(size_t)G4 * HH];
__device__ __nv_bfloat16 g_xg[(size_t)M_NT * WD];
__device__ float g_XWx[(size_t)M_NT * G4];
__device__ __nv_bfloat16 g_h0b[NB * HH];
__device__ float g_c[NB * HH];
__device__ float g_bi[G4];
__device__ float g_part[(size_t)M_NT * NTILES_V];
__device__ float g_nll[M_NT];
__device__ int   g_rows[M_NT];
__device__ int   g_tgt[M_NT];
__device__ int   g_is64;
__device__ int   g_bar_cnt;
__device__ int   g_bar_phase;
__device__ int   g_w8done[NTILES_V];
__device__ int   g_h0done;
__device__ int   g_xwx_done[TT];

// ---------------- small helpers ----------------
__device__ __forceinline__ float sigmoidf_(float x) { return 1.f / (1.f + __expf(-x)); }
__device__ __forceinline__ uint32_t smem_u32(const void* p) {
    return (uint32_t)__cvta_generic_to_shared(p);
}
__device__ __forceinline__ void cp16a(uint32_t dst, const void* src) {
    asm volatile("cp.async.cg.shared.global [%0], [%1], 16;"
                 :: "r"(dst), "l"(src));
}
__device__ __forceinline__ void cp_commit() { asm volatile("cp.async.commit_group;"); }
template<int N> __device__ __forceinline__ void cp_wait() {
    asm volatile("cp.async.wait_group %0;" :: "n"(N));
}
__device__ __forceinline__ void ldsm4(uint32_t& r0, uint32_t& r1, uint32_t& r2, uint32_t& r3, uint32_t addr) {
    asm volatile("ldmatrix.sync.aligned.m8n8.x4.shared.b16 {%0,%1,%2,%3}, [%4];"
                 : "=r"(r0), "=r"(r1), "=r"(r2), "=r"(r3) : "r"(addr));
}
__device__ __forceinline__ void ldsm2(uint32_t& r0, uint32_t& r1, uint32_t addr) {
    asm volatile("ldmatrix.sync.aligned.m8n8.x2.shared.b16 {%0,%1}, [%2];"
                 : "=r"(r0), "=r"(r1) : "r"(addr));
}
__device__ __forceinline__ void mma16816(float* c, const uint32_t* a, const uint32_t* b) {
    asm volatile("mma.sync.aligned.m16n8k16.row.col.f32.bf16.bf16.f32 "
                 "{%0,%1,%2,%3}, {%4,%5,%6,%7}, {%8,%9}, {%0,%1,%2,%3};"
                 : "+f"(c[0]), "+f"(c[1]), "+f"(c[2]), "+f"(c[3])
                 : "r"(a[0]), "r"(a[1]), "r"(a[2]), "r"(a[3]), "r"(b[0]), "r"(b[1]));
}
__device__ __forceinline__ void mma16832s8(int* c, const uint32_t* a, const uint32_t* b) {
    asm volatile("mma.sync.aligned.m16n8k32.row.col.s32.s8.s8.s32 "
                 "{%0,%1,%2,%3}, {%4,%5,%6,%7}, {%8,%9}, {%0,%1,%2,%3};"
                 : "+r"(c[0]), "+r"(c[1]), "+r"(c[2]), "+r"(c[3])
                 : "r"(a[0]), "r"(a[1]), "r"(a[2]), "r"(a[3]), "r"(b[0]), "r"(b[1]));
}
__device__ __forceinline__ signed char q8h(float x) {
    return (signed char)__float2int_rn(x * HSC);
}
__device__ __forceinline__ signed char q8w(float x) {
    int v = __float2int_rn(x * WSC);
    v = v > 127 ? 127 : (v < -127 ? -127 : v);
    return (signed char)v;
}

// ---------------- caption dtype detection + index build (t-major) ----------
__global__ void detect_kernel(const unsigned int* __restrict__ w) {
    __shared__ int found;
    if (threadIdx.x == 0) found = 0;
    __syncthreads();
    for (int i = threadIdx.x; i < NTOK / 2; i += blockDim.x)
        if (w[2 * i + 1] != 0u) found = 1;
    __syncthreads();
    if (threadIdx.x == 0) g_is64 = (found == 0) ? 1 : 0;
}

__global__ void build_idx_kernel(const void* __restrict__ caps) {
    int m = blockIdx.x * blockDim.x + threadIdx.x;
    if (m < NTILES_V) g_w8done[m] = 0;
    if (m < TT) g_xwx_done[m] = 0;
    if (m == M_NT - 1) { g_bar_cnt = 0; g_bar_phase = 0; g_h0done = 0; }
    if (m >= M_NT) return;
    int t = m >> 7, n = m & 127;            // t-major
    int ci, co;
    if (g_is64) {
        const long long* c = (const long long*)caps;
        ci = (int)c[n * 33 + t];  co = (int)c[n * 33 + t + 1];
    } else {
        const int* c = (const int*)caps;
        ci = c[n * 33 + t];       co = c[n * 33 + t + 1];
    }
    g_rows[m] = ci;  g_tgt[m] = co;
}

// ---------------- merged prep: bias | transT(Wx) | transT(Wh) | gather -----
// roles: [0,1) bias | [1,513) Wx transT | [513,1537) Wh transT | [1537,5633) gather
__global__ void prep_kernel(const float* __restrict__ Wx, const float* __restrict__ Wh,
                            const float* __restrict__ bb, const float* __restrict__ We) {
    __shared__ float tile[32][33];
    int role = blockIdx.x;
    int tid = threadIdx.x;

    if (role == 0) {
        for (int np = tid; np < G4; np += 256) {
            int j = np >> 2, g = np & 3;
            g_bi[np] = bb[g * HH + j];
        }
    } else if (role < 1537) {
        const float* in;
        __nv_bfloat16* out;
        int v, K;
        if (role < 513) { v = role - 1;   in = Wx; out = g_WxiT; K = WD; }
        else            { v = role - 513; in = Wh; out = g_WhiT; K = HH; }
        int np0 = (v & 63) * 32, k0 = (v >> 6) * 32;
        int tx = tid & 31, ty = tid >> 5;
#pragma unroll
        for (int r = 0; r < 4; r++)
            tile[ty + r * 8][tx] = in[(size_t)(k0 + ty + r * 8) * G4 + np0 + tx];
        __syncthreads();
#pragma unroll
        for (int r = 0; r < 4; r++) {
            int npl = ty + r * 8;
            int np = np0 + npl;
            int g = np >> 9, j = np & 511;
            int n = (j << 2) + g;
            out[(size_t)n * K + k0 + tx] = __float2bfloat16(tile[tx][npl]);
        }
    } else {
        int idx = (role - 1537) * 256 + tid;
        int m = idx >> 8, k = idx & (WD - 1);
        g_xg[idx] = __float2bfloat16(We[(size_t)g_rows[m] * WD + k]);
    }
}

// ============================================================================
// MEGA: h0 [0,32) | LSTM [32,96) | convW [96,346) | XWx [346,858) | vocab rest
// ============================================================================
__global__ void __launch_bounds__(256)
mega_kernel(const float* __restrict__ features, const float* __restrict__ W_proj,
            const float* __restrict__ b_proj,
            const float* __restrict__ Wv, const float* __restrict__ bv) {
    extern __shared__ __align__(16) char dynsm[];
    int role = blockIdx.x;
    int tid = threadIdx.x;
    int lane = tid & 31, wid = tid >> 5;

    if (role < R_LSTM) {
        // ---------------- h0 worker: BM=32 BN=64 BK=16 TM=2 TN=4 -----------
        int r = role - R_H0;
        int m0 = (r >> 3) * 32, n0 = (r & 7) * 64;
        float (*As)[33] = (float (*)[33])dynsm;
        float (*Bs)[64] = (float (*)[64])(dynsm + 16 * 33 * 4);
        int tx = tid & 15, ty = tid >> 4;

        float acc[2][4] = {};
        for (int k0 = 0; k0 < DF; k0 += 16) {
#pragma unroll
            for (int l = 0; l < 2; l++) {
                int idx = tid + l * 256;
                int k = idx & 15, m = idx >> 4;
                As[k][m] = features[(size_t)(m0 + m) * DF + k0 + k];
            }
#pragma unroll
            for (int l = 0; l < 4; l++) {
                int idx = tid + l * 256;
                int n = idx & 63, k = idx >> 6;
                Bs[k][n] = W_proj[(size_t)(k0 + k) * HH + n0 + n];
            }
            __syncthreads();
#pragma unroll
            for (int kk = 0; kk < 16; kk++) {
                float a0 = As[kk][ty * 2], a1 = As[kk][ty * 2 + 1];
                float b[4];
#pragma unroll
                for (int j2 = 0; j2 < 4; j2++) b[j2] = Bs[kk][tx * 4 + j2];
#pragma unroll
                for (int j2 = 0; j2 < 4; j2++) { acc[0][j2] += a0 * b[j2]; acc[1][j2] += a1 * b[j2]; }
            }
            __syncthreads();
        }
#pragma unroll
        for (int i = 0; i < 2; i++)
#pragma unroll
            for (int j2 = 0; j2 < 4; j2++) {
                int n = n0 + tx * 4 + j2;
                g_h0b[(size_t)(m0 + ty * 2 + i) * HH + n] =
                    __float2bfloat16(acc[i][j2] + b_proj[n]);
            }
        __threadfence();
        __syncthreads();
        if (tid == 0) atomicAdd(&g_h0done, 1);

    } else if (role < R_CONVW) {
        // ---------------- LSTM worker ----------------
        uint32_t bsU = smem_u32(dynsm);
        uint32_t asU = bsU + L_AS_O;
        int wm = wid >> 2, wn = wid & 3;
        int n0 = (role - R_LSTM) * 32;

#pragma unroll
        for (int l = 0; l < 8; l++) {
            int idx = tid + l * 256;
            int row = idx >> 6, ch = idx & 63;
            cp16a(bsU + row * 1040 + ch * 16, g_WhiT + (size_t)(n0 + row) * HH + ch * 8);
        }
        cp_commit(); cp_wait<0>();
        __syncthreads();

        // wait for h0
        if (tid == 0) {
            while (*(volatile int*)&g_h0done < 32) __nanosleep(64);
            __threadfence();
        }
        __syncthreads();

        int cbase = n0 + wn * 8 + 2 * (lane & 3);
        int j = cbase >> 2;

        for (int t = 0; t < TT; t++) {
            const __nv_bfloat16* Aptr = (t == 0) ? g_h0b : (g_hb + (size_t)(t - 1) * 128 * HH);

            auto loadA = [&](int s, int k0) {
#pragma unroll
                for (int l = 0; l < 2; l++) {
                    int idx = tid + l * 256;
                    int row = idx >> 2, ch = idx & 3;
                    cp16a(asU + s * 10240 + row * 80 + ch * 16,
                          Aptr + (size_t)row * HH + k0 + ch * 8);
                }
                cp_commit();
            };

            float acc[4][4];
#pragma unroll
            for (int a = 0; a < 4; a++)
#pragma unroll
                for (int c = 0; c < 4; c++) acc[a][c] = 0.f;

            loadA(0, 0);
            loadA(1, 32);

            for (int it = 0; it < 16; it++) {
                if (it < 15) cp_wait<1>(); else cp_wait<0>();
                __syncthreads();
                if (it + 2 < 16) loadA((it + 2) % 3, (it + 2) * 32);
                int s = it % 3;
#pragma unroll
                for (int ks = 0; ks < 2; ks++) {
                    uint32_t a[4][4], b[2];
#pragma unroll
                    for (int mf = 0; mf < 4; mf++) {
                        int row = wm * 64 + mf * 16 + (lane & 15);
                        ldsm4(a[mf][0], a[mf][1], a[mf][2], a[mf][3],
                              asU + s * 10240 + row * 80 + (ks * 16 + (lane >> 4) * 8) * 2);
                    }
                    {
                        int row = wn * 8 + (lane & 7);
                        ldsm2(b[0], b[1],
                              bsU + row * 1040 + (it * 32 + ks * 16 + ((lane >> 3) & 1) * 8) * 2);
                    }
#pragma unroll
                    for (int mf = 0; mf < 4; mf++)
                        mma16816(acc[mf], a[mf], b);
                }
            }

            // wait for this step's XWx chunk
            if (tid == 0) {
                while (*(volatile int*)&g_xwx_done[t] < 16) __nanosleep(64);
                __threadfence();
            }
            __syncthreads();

#pragma unroll
            for (int mf = 0; mf < 4; mf++) {
                int r = wm * 64 + mf * 16 + (lane >> 2);
                float2 x0 = *(const float2*)&g_XWx[(size_t)(t * 128 + r) * G4 + cbase];
                float2 x1 = *(const float2*)&g_XWx[(size_t)(t * 128 + r + 8) * G4 + cbase];
                float v0 = acc[mf][0] + x0.x, v1 = acc[mf][1] + x0.y;
                float v2 = acc[mf][2] + x1.x, v3 = acc[mf][3] + x1.y;
                float e0 = __shfl_xor_sync(0xffffffffu, v0, 1);
                float e1 = __shfl_xor_sync(0xffffffffu, v1, 1);
                float e2 = __shfl_xor_sync(0xffffffffu, v2, 1);
                float e3 = __shfl_xor_sync(0xffffffffu, v3, 1);
                if (!(lane & 1)) {
                    {
                        float i_ = sigmoidf_(v0), f_ = sigmoidf_(v1);
                        float o_ = sigmoidf_(e0), gg = tanhf(e1);
                        float cp = t ? g_c[r * HH + j] : 0.f;
                        float cn = f_ * cp + i_ * gg;
                        float hv = o_ * tanhf(cn);
                        g_c[r * HH + j] = cn;
                        size_t hi = (size_t)(t * 128 + r) * HH + j;
                        g_hb[hi] = __float2bfloat16(hv);
                        g_h8[hi] = q8h(hv);
                    }
                    {
                        int r8 = r + 8;
                        float i_ = sigmoidf_(v2), f_ = sigmoidf_(v3);
                        float o_ = sigmoidf_(e2), gg = tanhf(e3);
                        float cp = t ? g_c[r8 * HH + j] : 0.f;
                        float cn = f_ * cp + i_ * gg;
                        float hv = o_ * tanhf(cn);
                        g_c[r8 * HH + j] = cn;
                        size_t hi = (size_t)(t * 128 + r8) * HH + j;
                        g_hb[hi] = __float2bfloat16(hv);
                        g_h8[hi] = q8h(hv);
                    }
                }
            }

            __syncthreads();
            if (tid == 0) {
                __threadfence();
                int old = atomicAdd(&g_bar_cnt, 1);
                if (old == NBLK * (t + 1) - 1)
                    atomicExch(&g_bar_phase, t + 1);
                while (*(volatile int*)&g_bar_phase < t + 1) __nanosleep(64);
                __threadfence();
            }
            __syncthreads();
        }
    } else if (role < R_XWX) {
        // ---------------- convW worker ----------------
        int b = role - R_CONVW;
        float (*tile)[33] = (float (*)[33])dynsm;
        int tx = tid & 31, ty = tid >> 5;
        for (int kt = 0; kt < 16; kt++) {
            int k0 = kt * 32;
#pragma unroll
            for (int ns = 0; ns < 4; ns++) {
                int n0b = b * 128 + ns * 32;
                __syncthreads();
#pragma unroll
                for (int r = 0; r < 4; r++)
                    tile[ty + r * 8][tx] = Wv[(size_t)(k0 + ty + r * 8) * VV + n0b + tx];
                __syncthreads();
#pragma unroll
                for (int r = 0; r < 4; r++) {
                    int n = ty + r * 8;
                    float w = tile[tx][n];
                    g_wt[(size_t)(n0b + n) * HH + k0 + tx] = __float2bfloat16(w);
                    g_w8[(size_t)(n0b + n) * HH + k0 + tx] = q8w(w);
                }
            }
        }
        __threadfence();
        __syncthreads();
        if (tid == 0) atomicExch(&g_w8done[b], 1);
    } else if (role < R_VOC) {
        // ---------------- XWx worker (t-ascending) ----------------
        int v = role - R_XWX;
        int m0 = (v >> 4) * 128, n0 = (v & 15) * 128;

        uint32_t aU = smem_u32(dynsm);
        uint32_t bU = aU + 2 * 128 * 80;
        int wm = wid & 1, wn = wid >> 1;

        float acc[4][4][4];
#pragma unroll
        for (int a = 0; a < 4; a++)
#pragma unroll
            for (int b2 = 0; b2 < 4; b2++)
#pragma unroll
                for (int c = 0; c < 4; c++) acc[a][b2][c] = 0.f;

        auto loadA = [&](int s, int k0) {
#pragma unroll
            for (int l = 0; l < 2; l++) {
                int idx = tid + l * 256;
                int row = idx >> 2, ch = idx & 3;
                cp16a(aU + s * 10240 + row * 80 + ch * 16,
                      g_xg + (size_t)(m0 + row) * WD + k0 + ch * 8);
            }
        };
        auto loadB = [&](int s, int k0) {
#pragma unroll
            for (int l = 0; l < 2; l++) {
                int idx = tid + l * 256;
                int row = idx >> 2, ch = idx & 3;
                cp16a(bU + s * 10240 + row * 80 + ch * 16,
                      g_WxiT + (size_t)(n0 + row) * WD + k0 + ch * 8);
            }
        };
        loadA(0, 0); loadB(0, 0); cp_commit();

        constexpr int NIT = WD / 32;  // 8
        for (int it = 0; it < NIT; it++) {
            if (it + 1 < NIT) {
                int s = (it + 1) & 1;
                loadA(s, (it + 1) * 32); loadB(s, (it + 1) * 32);
                cp_commit(); cp_wait<1>();
            } else cp_wait<0>();
            __syncthreads();
            int s = it & 1;
#pragma unroll
            for (int ks = 0; ks < 2; ks++) {
                uint32_t a[4][4], b[4][2];
#pragma unroll
                for (int mf = 0; mf < 4; mf++) {
                    int row = wm * 64 + mf * 16 + (lane & 15);
                    ldsm4(a[mf][0], a[mf][1], a[mf][2], a[mf][3],
                          aU + s * 10240 + row * 80 + (ks * 16 + (lane >> 4) * 8) * 2);
                }
#pragma unroll
                for (int nf = 0; nf < 4; nf++) {
                    int row = wn * 32 + nf * 8 + (lane & 7);
                    ldsm2(b[nf][0], b[nf][1],
                          bU + s * 10240 + row * 80 + (ks * 16 + ((lane >> 3) & 1) * 8) * 2);
                }
#pragma unroll
                for (int mf = 0; mf < 4; mf++)
#pragma unroll
                    for (int nf = 0; nf < 4; nf++)
                        mma16816(acc[mf][nf], a[mf], b[nf]);
            }
            __syncthreads();
        }

#pragma unroll
        for (int mf = 0; mf < 4; mf++) {
            int r = m0 + wm * 64 + mf * 16 + (lane >> 2);
#pragma unroll
            for (int nf = 0; nf < 4; nf++) {
                int c = n0 + wn * 32 + nf * 8 + 2 * (lane & 3);
                float b0 = g_bi[c], b1 = g_bi[c + 1];
                float2 v0 = {acc[mf][nf][0] + b0, acc[mf][nf][1] + b1};
                float2 v1 = {acc[mf][nf][2] + b0, acc[mf][nf][3] + b1};
                *(float2*)&g_XWx[(size_t)r * G4 + c] = v0;
                *(float2*)&g_XWx[(size_t)(r + 8) * G4 + c] = v1;
            }
        }
        __threadfence();
        __syncthreads();
        if (tid == 0) atomicAdd(&g_xwx_done[v >> 4], 1);
    } else {
        // ---------------- vocab consumer (t, ntile) ----------------
        int v = role - R_VOC;
        int t = v / NTILES_V, ntile = v % NTILES_V;
        int m0 = t * 128, n0 = ntile * VBN;

        if (tid == 0) {
            while (*(volatile int*)&g_bar_phase < t + 1 ||
                   *(volatile int*)&g_w8done[ntile] == 0)
                __nanosleep(128);
            __threadfence();
        }
        __syncthreads();

        uint32_t aU = smem_u32(dynsm);
        uint32_t bU = aU + V_AS_B;
        float (*sred)[VBM] = (float (*)[VBM])(dynsm + V_SR_O);
        int wm = wid & 1, wn = wid >> 1;

        int acc[4][4][4];
#pragma unroll
        for (int a = 0; a < 4; a++)
#pragma unroll
            for (int b2 = 0; b2 < 4; b2++)
#pragma unroll
                for (int c = 0; c < 4; c++) acc[a][b2][c] = 0;

        auto loadAB = [&](int s, int k0) {
#pragma unroll
            for (int l = 0; l < 2; l++) {
                int idx = tid + l * 256;
                int row = idx >> 2, ch = idx & 3;
                cp16a(aU + s * 10240 + row * 80 + ch * 16,
                      g_h8 + (size_t)(m0 + row) * HH + k0 + ch * 16);
                cp16a(bU + s * 10240 + row * 80 + ch * 16,
                      g_w8 + (size_t)(n0 + row) * HH + k0 + ch * 16);
            }
            cp_commit();
        };

        loadAB(0, 0);
        loadAB(1, 64);

        constexpr int NIT = HH / 64;  // 8
        for (int it = 0; it < NIT; it++) {
            if (it < NIT - 1) cp_wait<1>(); else cp_wait<0>();
            __syncthreads();
            if (it + 2 < NIT) loadAB((it + 2) % 3, (it + 2) * 64);
            int s = it % 3;
#pragma unroll
            for (int ks = 0; ks < 2; ks++) {
                uint32_t a[4][4], b[4][2];
#pragma unroll
                for (int mf = 0; mf < 4; mf++) {
                    int row = wm * 64 + mf * 16 + (lane & 15);
                    ldsm4(a[mf][0], a[mf][1], a[mf][2], a[mf][3],
                          aU + s * 10240 + row * 80 + ks * 32 + (lane >> 4) * 16);
                }
#pragma unroll
                for (int nf = 0; nf < 4; nf++) {
                    int row = wn * 32 + nf * 8 + (lane & 7);
                    ldsm2(b[nf][0], b[nf][1],
                          bU + s * 10240 + row * 80 + ks * 32 + ((lane >> 3) & 1) * 16);
                }
#pragma unroll
                for (int mf = 0; mf < 4; mf++)
#pragma unroll
                    for (int nf = 0; nf < 4; nf++)
                        mma16832s8(acc[mf][nf], a[mf], b[nf]);
            }
        }

        const float INV = 1.f / (HSC * WSC);
        float rowsum[4][2] = {};
#pragma unroll
        for (int nf = 0; nf < 4; nf++) {
            int nb_ = n0 + wn * 32 + nf * 8 + 2 * (lane & 3);
            float b0 = bv[nb_], b1 = bv[nb_ + 1];
#pragma unroll
            for (int mf = 0; mf < 4; mf++) {
                rowsum[mf][0] += __expf(fmaf((float)acc[mf][nf][0], INV, b0))
                               + __expf(fmaf((float)acc[mf][nf][1], INV, b1));
                rowsum[mf][1] += __expf(fmaf((float)acc[mf][nf][2], INV, b0))
                               + __expf(fmaf((float)acc[mf][nf][3], INV, b1));
            }
        }
#pragma unroll
        for (int mf = 0; mf < 4; mf++)
#pragma unroll
            for (int h = 0; h < 2; h++) {
                rowsum[mf][h] += __shfl_xor_sync(0xffffffffu, rowsum[mf][h], 1);
                rowsum[mf][h] += __shfl_xor_sync(0xffffffffu, rowsum[mf][h], 2);
            }
        __syncthreads();
        if ((lane & 3) == 0) {
#pragma unroll
            for (int mf = 0; mf < 4; mf++) {
                int r = wm * 64 + mf * 16 + (lane >> 2);
                sred[wn][r]     = rowsum[mf][0];
                sred[wn][r + 8] = rowsum[mf][1];
            }
        }
        __syncthreads();
        if (tid < VBM) {
            float s = sred[0][tid] + sred[1][tid] + sred[2][tid] + sred[3][tid];
            g_part[(size_t)(m0 + tid) * NTILES_V + ntile] = s;
        }
    }
}

// ---------------- merged target-score + nll ----------------
__global__ void nll_tsc_kernel(const float* __restrict__ bv) {
    int w = (blockIdx.x * blockDim.x + threadIdx.x) >> 5;
    int lane = threadIdx.x & 31;
    if (w >= M_NT) return;
    int tgt = g_tgt[w];

    const uint4* h4 = (const uint4*)(g_hb + (size_t)w * HH);
    const uint4* w4 = (const uint4*)(g_wt + (size_t)tgt * HH);
    float ts = 0.f;
#pragma unroll
    for (int i = 0; i < 2; i++) {
        uint4 a = h4[lane + i * 32];
        uint4 b = w4[lane + i * 32];
        const uint32_t* ap = &a.x;
        const uint32_t* bp = &b.x;
#pragma unroll
        for (int q = 0; q < 4; q++) {
            float2 fa = __bfloat1622float2(*(const __nv_bfloat162*)&ap[q]);
            float2 fb = __bfloat1622float2(*(const __nv_bfloat162*)&bp[q]);
            ts += fa.x * fb.x + fa.y * fb.y;
        }
    }
    const float* p = g_part + (size_t)w * NTILES_V;
    float se = 0.f;
    for (int i = lane; i < NTILES_V; i += 32) se += p[i];
#pragma unroll
    for (int off = 16; off; off >>= 1) {
        ts += __shfl_down_sync(0xffffffffu, ts, off);
        se += __shfl_down_sync(0xffffffffu, se, off);
    }
    if (lane == 0)
        g_nll[w] = (tgt != 0) ? (logf(se) - (ts + bv[tgt])) : 0.f;
}

__global__ void loss_kernel(float* __restrict__ out) {
    __shared__ float sm[256];
    float s = 0.f;
    for (int i = threadIdx.x; i < M_NT; i += 256) s += g_nll[i];
    sm[threadIdx.x] = s;
    __syncthreads();
    for (int off = 128; off; off >>= 1) {
        if (threadIdx.x < off) sm[threadIdx.x] += sm[threadIdx.x + off];
        __syncthreads();
    }
    if (threadIdx.x == 0) out[0] = sm[0] / (float)NB;
}

// ---------------- launch ----------------
extern "C" void kernel_launch(void* const* d_in, const int* in_sizes, int n_in,
                              void* d_out, int out_size) {
    const float* features = (const float*)d_in[0];
    const void*  captions =               d_in[1];
    const float* W_proj   = (const float*)d_in[2];
    const float* b_proj   = (const float*)d_in[3];
    const float* W_embed  = (const float*)d_in[4];
    const float* Wx       = (const float*)d_in[5];
    const float* Wh       = (const float*)d_in[6];
    const float* bb       = (const float*)d_in[7];
    const float* W_vocab  = (const float*)d_in[8];
    const float* b_vocab  = (const float*)d_in[9];
    float* out = (float*)d_out;

    cudaFuncSetAttribute(mega_kernel,
                         cudaFuncAttributeMaxDynamicSharedMemorySize, M_SMEM);

    // 0. indices + flag resets, merged prep
    detect_kernel<<<1, 256>>>((const unsigned int*)captions);
    build_idx_kernel<<<(M_NT + 255) / 256, 256>>>(captions);
    prep_kernel<<<1537 + M_NT * WD / 256, 256>>>(Wx, Wh, bb, W_embed);

    // 1. MEGA: h0 + LSTM + convW + XWx + vocab, overlapped via progress flags
    mega_kernel<<<R_END, 256, M_SMEM>>>(features, W_proj, b_proj, W_vocab, b_vocab);

    // 2. merged tscore+nll, final loss
    nll_tsc_kernel<<<M_NT / 4, 128>>>(b_vocab);
    loss_kernel<<<1, 256>>>(out);
}